// round 1
// baseline (speedup 1.0000x reference)
#include <cuda_runtime.h>
#include <math.h>

// Problem constants
#define DM   1024          // d_model
#define NH   16            // heads
#define HD   64            // head dim
#define DFF  4096
#define BB   2             // batch
#define LL   2048          // seq len
#define MTOT (BB*LL)       // 4096 rows

// ---------------- scratch (static device globals; allocation-free) ----------
__device__ float g_Q[(size_t)NH*BB*LL*HD];     // [bh][L][HD]
__device__ float g_K[(size_t)NH*BB*LL*HD];
__device__ float g_V[(size_t)NH*BB*LL*HD];
__device__ float g_attn[(size_t)MTOT*DM];      // merged-head attention output
__device__ float g_proj[(size_t)MTOT*DM];      // attn @ Wo + bo
__device__ float g_x[(size_t)MTOT*DM];         // LN1 output
__device__ float g_ff1[(size_t)MTOT*DFF];      // gelu(x @ W1 + b1)
__device__ float g_ff2[(size_t)MTOT*DM];       // ff1 @ W2 + b2

// ---------------- SGEMM: C = A[MxK] @ B[KxN] + bias, epilogue variants ------
// EPI 0: plain   EPI 1: exact GELU  EPI 2: split-heads layout [b*16+h][l][hd]
template<int EPI>
__global__ __launch_bounds__(256)
void sgemm_k(const float* __restrict__ A, const float* __restrict__ B,
             const float* __restrict__ bias, float* __restrict__ C,
             int M, int N, int K)
{
    __shared__ float As[16][128];   // [k][m]
    __shared__ float Bs[16][128];   // [k][n]

    const int tid = threadIdx.x;
    const int tx = tid & 15, ty = tid >> 4;
    const int bx = blockIdx.x, by = blockIdx.y;

    const float* Ab = A + (size_t)by * 128 * K;
    const float* Bb = B + (size_t)bx * 128;

    float acc[8][8];
    #pragma unroll
    for (int i = 0; i < 8; i++)
        #pragma unroll
        for (int j = 0; j < 8; j++) acc[i][j] = 0.f;

    for (int k0 = 0; k0 < K; k0 += 16) {
        #pragma unroll
        for (int i = 0; i < 2; i++) {
            int idx = tid + i * 256;
            int ar = idx >> 2, ac = (idx & 3) << 2;
            float4 av = *(const float4*)(Ab + (size_t)ar * K + k0 + ac);
            As[ac + 0][ar] = av.x; As[ac + 1][ar] = av.y;
            As[ac + 2][ar] = av.z; As[ac + 3][ar] = av.w;
            int br = idx >> 5, bc = (idx & 31) << 2;
            float4 bv = *(const float4*)(Bb + (size_t)(k0 + br) * N + bc);
            *(float4*)&Bs[br][bc] = bv;
        }
        __syncthreads();
        #pragma unroll
        for (int kk = 0; kk < 16; kk++) {
            float af[8], bf[8];
            #pragma unroll
            for (int i = 0; i < 8; i++) af[i] = As[kk][ty * 8 + i];
            #pragma unroll
            for (int j = 0; j < 8; j++) bf[j] = Bs[kk][tx * 8 + j];
            #pragma unroll
            for (int i = 0; i < 8; i++)
                #pragma unroll
                for (int j = 0; j < 8; j++)
                    acc[i][j] = fmaf(af[i], bf[j], acc[i][j]);
        }
        __syncthreads();
    }

    const int row0 = by * 128 + ty * 8;
    const int col0 = bx * 128 + tx * 8;
    #pragma unroll
    for (int i = 0; i < 8; i++) {
        int m = row0 + i;
        #pragma unroll
        for (int j = 0; j < 8; j += 4) {
            float4 v;
            v.x = acc[i][j + 0] + bias[col0 + j + 0];
            v.y = acc[i][j + 1] + bias[col0 + j + 1];
            v.z = acc[i][j + 2] + bias[col0 + j + 2];
            v.w = acc[i][j + 3] + bias[col0 + j + 3];
            if (EPI == 1) {           // exact GELU: x * Phi(x)
                v.x *= normcdff(v.x);
                v.y *= normcdff(v.y);
                v.z *= normcdff(v.z);
                v.w *= normcdff(v.w);
            }
            if (EPI == 2) {           // split heads: [b*16+h][l][hd]
                int n = col0 + j;
                int b = m >> 11, l = m & 2047;
                int h = n >> 6,  hd = n & 63;
                float4* dst = (float4*)(C + ((size_t)((b << 4) + h) * LL + l) * HD + hd);
                *dst = v;
            } else {
                *(float4*)(C + (size_t)m * N + col0 + j) = v;
            }
        }
    }
}

// ---------------- flash attention (fp32, online softmax) --------------------
// grid: (L/64, B*H), block 64. One query per thread, Hd=64 in registers.
__global__ __launch_bounds__(64)
void flash_k(const float* __restrict__ Q, const float* __restrict__ K,
             const float* __restrict__ V, float* __restrict__ O)
{
    __shared__ float4 Ks[64 * 16];
    __shared__ float4 Vs[64 * 16];

    const int t  = threadIdx.x;
    const int bh = blockIdx.y;
    const int q  = blockIdx.x * 64 + t;

    const float4* Qr = (const float4*)(Q + ((size_t)bh * LL + q) * HD);
    float4 qr[16];
    #pragma unroll
    for (int i = 0; i < 16; i++) {
        qr[i] = Qr[i];
        qr[i].x *= 0.125f; qr[i].y *= 0.125f;   // 1/sqrt(64)
        qr[i].z *= 0.125f; qr[i].w *= 0.125f;
    }

    float m = -1e30f, l = 0.f;
    float4 ar[16];
    #pragma unroll
    for (int i = 0; i < 16; i++) ar[i] = make_float4(0.f, 0.f, 0.f, 0.f);

    const float4* Kb = (const float4*)(K + (size_t)bh * LL * HD);
    const float4* Vb = (const float4*)(V + (size_t)bh * LL * HD);

    for (int kt = 0; kt < LL / 64; kt++) {
        const float4* Kt = Kb + kt * 64 * 16;
        const float4* Vt = Vb + kt * 64 * 16;
        for (int i = t; i < 1024; i += 64) { Ks[i] = Kt[i]; Vs[i] = Vt[i]; }
        __syncthreads();

        for (int j = 0; j < 64; j++) {
            const float4* kr = &Ks[j * 16];
            float s = 0.f;
            #pragma unroll
            for (int kk = 0; kk < 16; kk++) {
                float4 kv = kr[kk];
                s = fmaf(qr[kk].x, kv.x, s);
                s = fmaf(qr[kk].y, kv.y, s);
                s = fmaf(qr[kk].z, kv.z, s);
                s = fmaf(qr[kk].w, kv.w, s);
            }
            if (s > m) {
                float f = __expf(m - s);
                m = s; l *= f;
                #pragma unroll
                for (int kk = 0; kk < 16; kk++) {
                    ar[kk].x *= f; ar[kk].y *= f; ar[kk].z *= f; ar[kk].w *= f;
                }
            }
            float p = __expf(s - m);
            l += p;
            const float4* vr = &Vs[j * 16];
            #pragma unroll
            for (int kk = 0; kk < 16; kk++) {
                float4 vv = vr[kk];
                ar[kk].x = fmaf(p, vv.x, ar[kk].x);
                ar[kk].y = fmaf(p, vv.y, ar[kk].y);
                ar[kk].z = fmaf(p, vv.z, ar[kk].z);
                ar[kk].w = fmaf(p, vv.w, ar[kk].w);
            }
        }
        __syncthreads();
    }

    const float inv = 1.f / l;
    const int b = bh >> 4, h = bh & 15;
    float4* Or = (float4*)(O + ((size_t)(b * LL + q)) * DM + h * HD);
    #pragma unroll
    for (int kk = 0; kk < 16; kk++) {
        float4 v = ar[kk];
        v.x *= inv; v.y *= inv; v.z *= inv; v.w *= inv;
        Or[kk] = v;
    }
}

// ---------------- fused residual add + LayerNorm ----------------------------
__global__ __launch_bounds__(256)
void add_ln_k(const float* __restrict__ A, const float* __restrict__ B,
              const float* __restrict__ gamma, const float* __restrict__ beta,
              float* __restrict__ out)
{
    const int row = blockIdx.x, t = threadIdx.x;
    const float4* a = (const float4*)(A + (size_t)row * DM);
    const float4* b = (const float4*)(B + (size_t)row * DM);
    float4 v = a[t], w = b[t];
    v.x += w.x; v.y += w.y; v.z += w.z; v.w += w.w;

    float s = v.x + v.y + v.z + v.w;
    float q = v.x * v.x + v.y * v.y + v.z * v.z + v.w * v.w;
    #pragma unroll
    for (int o = 16; o > 0; o >>= 1) {
        s += __shfl_xor_sync(0xffffffffu, s, o);
        q += __shfl_xor_sync(0xffffffffu, q, o);
    }
    __shared__ float ss[8], sq[8];
    const int wid = t >> 5, lane = t & 31;
    if (lane == 0) { ss[wid] = s; sq[wid] = q; }
    __syncthreads();
    s = 0.f; q = 0.f;
    #pragma unroll
    for (int i = 0; i < 8; i++) { s += ss[i]; q += sq[i]; }

    const float mean = s * (1.f / DM);
    const float var  = q * (1.f / DM) - mean * mean;
    const float rstd = rsqrtf(var + 1e-5f);

    const int c = t * 4;
    float4 g  = *(const float4*)(gamma + c);
    float4 be = *(const float4*)(beta + c);
    float4 o;
    o.x = (v.x - mean) * rstd * g.x + be.x;
    o.y = (v.y - mean) * rstd * g.y + be.y;
    o.z = (v.z - mean) * rstd * g.z + be.z;
    o.w = (v.w - mean) * rstd * g.w + be.w;
    ((float4*)(out + (size_t)row * DM))[t] = o;
}

// ---------------- launcher ---------------------------------------------------
extern "C" void kernel_launch(void* const* d_in, const int* in_sizes, int n_in,
                              void* d_out, int out_size)
{
    const float* src = (const float*)d_in[0];
    const float* Wq  = (const float*)d_in[1];  const float* bq = (const float*)d_in[2];
    const float* Wk  = (const float*)d_in[3];  const float* bk = (const float*)d_in[4];
    const float* Wv  = (const float*)d_in[5];  const float* bv = (const float*)d_in[6];
    const float* Wo  = (const float*)d_in[7];  const float* bo = (const float*)d_in[8];
    const float* W1  = (const float*)d_in[9];  const float* b1 = (const float*)d_in[10];
    const float* W2  = (const float*)d_in[11]; const float* b2 = (const float*)d_in[12];
    const float* gamma1 = (const float*)d_in[13]; const float* beta1 = (const float*)d_in[14];
    const float* gamma2 = (const float*)d_in[15]; const float* beta2 = (const float*)d_in[16];
    float* out = (float*)d_out;

    float *Qb, *Kb, *Vb, *attn, *proj, *x, *ff1, *ff2;
    cudaGetSymbolAddress((void**)&Qb,   g_Q);
    cudaGetSymbolAddress((void**)&Kb,   g_K);
    cudaGetSymbolAddress((void**)&Vb,   g_V);
    cudaGetSymbolAddress((void**)&attn, g_attn);
    cudaGetSymbolAddress((void**)&proj, g_proj);
    cudaGetSymbolAddress((void**)&x,    g_x);
    cudaGetSymbolAddress((void**)&ff1,  g_ff1);
    cudaGetSymbolAddress((void**)&ff2,  g_ff2);

    // QKV projections (split-heads epilogue)
    sgemm_k<2><<<dim3(DM / 128, MTOT / 128), 256>>>(src, Wq, bq, Qb, MTOT, DM, DM);
    sgemm_k<2><<<dim3(DM / 128, MTOT / 128), 256>>>(src, Wk, bk, Kb, MTOT, DM, DM);
    sgemm_k<2><<<dim3(DM / 128, MTOT / 128), 256>>>(src, Wv, bv, Vb, MTOT, DM, DM);

    // attention (merged-head output)
    flash_k<<<dim3(LL / 64, BB * NH), 64>>>(Qb, Kb, Vb, attn);

    // output projection
    sgemm_k<0><<<dim3(DM / 128, MTOT / 128), 256>>>(attn, Wo, bo, proj, MTOT, DM, DM);

    // x = LN(src + attn_proj)
    add_ln_k<<<MTOT, 256>>>(src, proj, gamma1, beta1, x);

    // FF
    sgemm_k<1><<<dim3(DFF / 128, MTOT / 128), 256>>>(x, W1, b1, ff1, MTOT, DFF, DM);
    sgemm_k<0><<<dim3(DM / 128, MTOT / 128), 256>>>(ff1, W2, b2, ff2, MTOT, DM, DFF);

    // out = LN(x + ff)
    add_ln_k<<<MTOT, 256>>>(x, ff2, gamma2, beta2, out);
}

// round 3
// speedup vs baseline: 1.4693x; 1.4693x over previous
#include <cuda_runtime.h>
#include <math.h>
#include <cstdint>

// Problem constants
#define DM   1024
#define NH   16
#define HD   64
#define DFF  4096
#define BB   2
#define LL   2048
#define MTOT (BB*LL)       // 4096 rows

// ---------------- scratch (static device globals; allocation-free) ----------
__device__ float g_Q[(size_t)NH*BB*LL*HD];
__device__ float g_K[(size_t)NH*BB*LL*HD];
__device__ float g_V[(size_t)NH*BB*LL*HD];
__device__ float g_attn[(size_t)MTOT*DM];
__device__ float g_proj[(size_t)MTOT*DM];
__device__ float g_x[(size_t)MTOT*DM];
__device__ float g_ff1[(size_t)MTOT*DFF];
__device__ float g_ff2[(size_t)MTOT*DM];

// ---------------- helpers ----------------------------------------------------
__device__ __forceinline__ uint32_t f2tf32(float f) {
    uint32_t u;
    asm("cvt.rna.tf32.f32 %0, %1;" : "=r"(u) : "f"(f));
    return u;
}

__device__ __forceinline__ void mma_tf32(float* d, const uint32_t* a, const uint32_t* b) {
    asm volatile(
        "mma.sync.aligned.m16n8k8.row.col.f32.tf32.tf32.f32 "
        "{%0,%1,%2,%3}, {%4,%5,%6,%7}, {%8,%9}, {%0,%1,%2,%3};"
        : "+f"(d[0]), "+f"(d[1]), "+f"(d[2]), "+f"(d[3])
        : "r"(a[0]), "r"(a[1]), "r"(a[2]), "r"(a[3]), "r"(b[0]), "r"(b[1]));
}

// ---------------- warp-mma TF32 GEMM: C[M,N] = A[M,K] @ B[K,N] + bias --------
// B used in native [K][N] layout (the dataset's [in,out] weights) - no transpose.
// EPI 0: plain   EPI 1: exact GELU   EPI 2: split-heads [b*16+h][l][hd]
// 256 threads = 8 warps in 4(m) x 2(n); each warp: 32x64 (2 x 8 m16n8k8 atoms).
#define KC 32                      // K chunk
#define APAD 132                   // 128 + 4 padding (bank spread)

template<int EPI>
__global__ __launch_bounds__(256)
void wm_gemm(const float* __restrict__ A, const float* __restrict__ B,
             const float* __restrict__ bias, float* __restrict__ C,
             int M, int N, int K)
{
    __shared__ uint32_t As[KC][APAD];   // [k][m], tf32
    __shared__ uint32_t Bs[KC][APAD];   // [k][n], tf32

    const int tid  = threadIdx.x;
    const int wid  = tid >> 5;
    const int lane = tid & 31;
    const int lg   = lane & 3;          // threadID_in_group
    const int grp  = lane >> 2;         // groupID
    const int n0 = blockIdx.x * 128;
    const int m0 = blockIdx.y * 128;
    const int wm = (wid & 3) * 32;      // warp m offset
    const int wn = (wid >> 2) * 64;     // warp n offset

    // A staging: thread -> row tid>>1 (0..127), 16 consecutive k at half*16
    const int arow = tid >> 1, ahalf = (tid & 1) * 16;
    const float* Ap = A + (size_t)(m0 + arow) * K + ahalf;
    // B staging: 4 passes, row (tid>>5)+p*8, col (tid&31)*4
    const int brow = tid >> 5, bcol = (lane) * 4;

    float d[2][8][4];
    #pragma unroll
    for (int i = 0; i < 2; i++)
        #pragma unroll
        for (int j = 0; j < 8; j++)
            #pragma unroll
            for (int q = 0; q < 4; q++) d[i][j][q] = 0.f;

    for (int k0 = 0; k0 < K; k0 += KC) {
        // ---- stage A[m0:m0+128][k0:k0+32] -> As[k][m] (tf32) ----
        #pragma unroll
        for (int i = 0; i < 4; i++) {
            float4 v = *(const float4*)(Ap + k0 + i * 4);
            int kk = ahalf + i * 4;
            As[kk + 0][arow] = f2tf32(v.x);
            As[kk + 1][arow] = f2tf32(v.y);
            As[kk + 2][arow] = f2tf32(v.z);
            As[kk + 3][arow] = f2tf32(v.w);
        }
        // ---- stage B[k0:k0+32][n0:n0+128] -> Bs[k][n] (tf32) ----
        #pragma unroll
        for (int p = 0; p < 4; p++) {
            int kk = brow + p * 8;
            float4 v = *(const float4*)(B + (size_t)(k0 + kk) * N + n0 + bcol);
            Bs[kk][bcol + 0] = f2tf32(v.x);
            Bs[kk][bcol + 1] = f2tf32(v.y);
            Bs[kk][bcol + 2] = f2tf32(v.z);
            Bs[kk][bcol + 3] = f2tf32(v.w);
        }
        __syncthreads();

        // ---- 4 k8-steps of mma ----
        #pragma unroll
        for (int ks = 0; ks < 4; ks++) {
            const int kr = ks * 8 + lg;
            uint32_t a[2][4], b[8][2];
            #pragma unroll
            for (int i = 0; i < 2; i++) {
                int mb = wm + i * 16 + grp;
                a[i][0] = As[kr][mb];
                a[i][1] = As[kr][mb + 8];
                a[i][2] = As[kr + 4][mb];
                a[i][3] = As[kr + 4][mb + 8];
            }
            #pragma unroll
            for (int j = 0; j < 8; j++) {
                int nb = wn + j * 8 + grp;
                b[j][0] = Bs[kr][nb];
                b[j][1] = Bs[kr + 4][nb];
            }
            #pragma unroll
            for (int i = 0; i < 2; i++)
                #pragma unroll
                for (int j = 0; j < 8; j++)
                    mma_tf32(d[i][j], a[i], b[j]);
        }
        __syncthreads();
    }

    // ---- epilogue ----
    #pragma unroll
    for (int i = 0; i < 2; i++) {
        const int r0 = m0 + wm + i * 16 + grp;
        #pragma unroll
        for (int j = 0; j < 8; j++) {
            const int c = n0 + wn + j * 8 + lg * 2;
            float2 v0, v1;
            v0.x = d[i][j][0] + bias[c];
            v0.y = d[i][j][1] + bias[c + 1];
            v1.x = d[i][j][2] + bias[c];
            v1.y = d[i][j][3] + bias[c + 1];
            if (EPI == 1) {
                v0.x *= normcdff(v0.x); v0.y *= normcdff(v0.y);
                v1.x *= normcdff(v1.x); v1.y *= normcdff(v1.y);
            }
            if (EPI == 2) {
                const int h = c >> 6, hd = c & 63;
                const int b0_ = r0 >> 11, l0 = r0 & 2047;
                const int r1 = r0 + 8;
                const int b1_ = r1 >> 11, l1 = r1 & 2047;
                *(float2*)(C + ((size_t)((b0_ << 4) + h) * LL + l0) * HD + hd) = v0;
                *(float2*)(C + ((size_t)((b1_ << 4) + h) * LL + l1) * HD + hd) = v1;
            } else {
                *(float2*)(C + (size_t)r0 * N + c) = v0;
                *(float2*)(C + (size_t)(r0 + 8) * N + c) = v1;
            }
        }
    }
}

// ---------------- flash attention (fp32, online softmax) --------------------
__global__ __launch_bounds__(64)
void flash_k(const float* __restrict__ Q, const float* __restrict__ K,
             const float* __restrict__ V, float* __restrict__ O)
{
    __shared__ float4 Ks[64 * 16];
    __shared__ float4 Vs[64 * 16];

    const int t  = threadIdx.x;
    const int bh = blockIdx.y;
    const int q  = blockIdx.x * 64 + t;

    const float4* Qr = (const float4*)(Q + ((size_t)bh * LL + q) * HD);
    float4 qr[16];
    #pragma unroll
    for (int i = 0; i < 16; i++) {
        qr[i] = Qr[i];
        qr[i].x *= 0.125f; qr[i].y *= 0.125f;
        qr[i].z *= 0.125f; qr[i].w *= 0.125f;
    }

    float m = -1e30f, l = 0.f;
    float4 ar[16];
    #pragma unroll
    for (int i = 0; i < 16; i++) ar[i] = make_float4(0.f, 0.f, 0.f, 0.f);

    const float4* Kb = (const float4*)(K + (size_t)bh * LL * HD);
    const float4* Vb = (const float4*)(V + (size_t)bh * LL * HD);

    for (int kt = 0; kt < LL / 64; kt++) {
        const float4* Kt = Kb + kt * 64 * 16;
        const float4* Vt = Vb + kt * 64 * 16;
        for (int i = t; i < 1024; i += 64) { Ks[i] = Kt[i]; Vs[i] = Vt[i]; }
        __syncthreads();

        for (int j = 0; j < 64; j++) {
            const float4* kr = &Ks[j * 16];
            float s = 0.f;
            #pragma unroll
            for (int kk = 0; kk < 16; kk++) {
                float4 kv = kr[kk];
                s = fmaf(qr[kk].x, kv.x, s);
                s = fmaf(qr[kk].y, kv.y, s);
                s = fmaf(qr[kk].z, kv.z, s);
                s = fmaf(qr[kk].w, kv.w, s);
            }
            if (s > m) {
                float f = __expf(m - s);
                m = s; l *= f;
                #pragma unroll
                for (int kk = 0; kk < 16; kk++) {
                    ar[kk].x *= f; ar[kk].y *= f; ar[kk].z *= f; ar[kk].w *= f;
                }
            }
            float p = __expf(s - m);
            l += p;
            const float4* vr = &Vs[j * 16];
            #pragma unroll
            for (int kk = 0; kk < 16; kk++) {
                float4 vv = vr[kk];
                ar[kk].x = fmaf(p, vv.x, ar[kk].x);
                ar[kk].y = fmaf(p, vv.y, ar[kk].y);
                ar[kk].z = fmaf(p, vv.z, ar[kk].z);
                ar[kk].w = fmaf(p, vv.w, ar[kk].w);
            }
        }
        __syncthreads();
    }

    const float inv = 1.f / l;
    const int b = bh >> 4, h = bh & 15;
    float4* Or = (float4*)(O + ((size_t)(b * LL + q)) * DM + h * HD);
    #pragma unroll
    for (int kk = 0; kk < 16; kk++) {
        float4 v = ar[kk];
        v.x *= inv; v.y *= inv; v.z *= inv; v.w *= inv;
        Or[kk] = v;
    }
}

// ---------------- fused residual add + LayerNorm ----------------------------
__global__ __launch_bounds__(256)
void add_ln_k(const float* __restrict__ A, const float* __restrict__ B,
              const float* __restrict__ gamma, const float* __restrict__ beta,
              float* __restrict__ out)
{
    const int row = blockIdx.x, t = threadIdx.x;
    const float4* a = (const float4*)(A + (size_t)row * DM);
    const float4* b = (const float4*)(B + (size_t)row * DM);
    float4 v = a[t], w = b[t];
    v.x += w.x; v.y += w.y; v.z += w.z; v.w += w.w;

    float s = v.x + v.y + v.z + v.w;
    float q = v.x * v.x + v.y * v.y + v.z * v.z + v.w * v.w;
    #pragma unroll
    for (int o = 16; o > 0; o >>= 1) {
        s += __shfl_xor_sync(0xffffffffu, s, o);
        q += __shfl_xor_sync(0xffffffffu, q, o);
    }
    __shared__ float ss[8], sq[8];
    const int wid = t >> 5, lane = t & 31;
    if (lane == 0) { ss[wid] = s; sq[wid] = q; }
    __syncthreads();
    s = 0.f; q = 0.f;
    #pragma unroll
    for (int i = 0; i < 8; i++) { s += ss[i]; q += sq[i]; }

    const float mean = s * (1.f / DM);
    const float var  = q * (1.f / DM) - mean * mean;
    const float rstd = rsqrtf(var + 1e-5f);

    const int c = t * 4;
    float4 g  = *(const float4*)(gamma + c);
    float4 be = *(const float4*)(beta + c);
    float4 o;
    o.x = (v.x - mean) * rstd * g.x + be.x;
    o.y = (v.y - mean) * rstd * g.y + be.y;
    o.z = (v.z - mean) * rstd * g.z + be.z;
    o.w = (v.w - mean) * rstd * g.w + be.w;
    ((float4*)(out + (size_t)row * DM))[t] = o;
}

// ---------------- launcher ---------------------------------------------------
extern "C" void kernel_launch(void* const* d_in, const int* in_sizes, int n_in,
                              void* d_out, int out_size)
{
    const float* src = (const float*)d_in[0];
    const float* Wq  = (const float*)d_in[1];  const float* bq = (const float*)d_in[2];
    const float* Wk  = (const float*)d_in[3];  const float* bk = (const float*)d_in[4];
    const float* Wv  = (const float*)d_in[5];  const float* bv = (const float*)d_in[6];
    const float* Wo  = (const float*)d_in[7];  const float* bo = (const float*)d_in[8];
    const float* W1  = (const float*)d_in[9];  const float* b1 = (const float*)d_in[10];
    const float* W2  = (const float*)d_in[11]; const float* b2 = (const float*)d_in[12];
    const float* gamma1 = (const float*)d_in[13]; const float* beta1 = (const float*)d_in[14];
    const float* gamma2 = (const float*)d_in[15]; const float* beta2 = (const float*)d_in[16];
    float* out = (float*)d_out;

    float *Qb, *Kb, *Vb, *attn, *proj, *x, *ff1, *ff2;
    cudaGetSymbolAddress((void**)&Qb,   g_Q);
    cudaGetSymbolAddress((void**)&Kb,   g_K);
    cudaGetSymbolAddress((void**)&Vb,   g_V);
    cudaGetSymbolAddress((void**)&attn, g_attn);
    cudaGetSymbolAddress((void**)&proj, g_proj);
    cudaGetSymbolAddress((void**)&x,    g_x);
    cudaGetSymbolAddress((void**)&ff1,  g_ff1);
    cudaGetSymbolAddress((void**)&ff2,  g_ff2);

    // QKV projections (split-heads epilogue); weights used natively [K][N]
    wm_gemm<2><<<dim3(DM / 128, MTOT / 128), 256>>>(src, Wq, bq, Qb, MTOT, DM, DM);
    wm_gemm<2><<<dim3(DM / 128, MTOT / 128), 256>>>(src, Wk, bk, Kb, MTOT, DM, DM);
    wm_gemm<2><<<dim3(DM / 128, MTOT / 128), 256>>>(src, Wv, bv, Vb, MTOT, DM, DM);

    // attention (merged-head output)
    flash_k<<<dim3(LL / 64, BB * NH), 64>>>(Qb, Kb, Vb, attn);

    // output projection
    wm_gemm<0><<<dim3(DM / 128, MTOT / 128), 256>>>(attn, Wo, bo, proj, MTOT, DM, DM);

    // x = LN(src + attn_proj)
    add_ln_k<<<MTOT, 256>>>(src, proj, gamma1, beta1, x);

    // FF
    wm_gemm<1><<<dim3(DFF / 128, MTOT / 128), 256>>>(x, W1, b1, ff1, MTOT, DFF, DM);
    wm_gemm<0><<<dim3(DM / 128, MTOT / 128), 256>>>(ff1, W2, b2, ff2, MTOT, DM, DFF);

    // out = LN(x + ff)
    add_ln_k<<<MTOT, 256>>>(x, ff2, gamma2, beta2, out);
}

// round 4
// speedup vs baseline: 1.8549x; 1.2624x over previous
#include <cuda_runtime.h>
#include <cuda_fp16.h>
#include <math.h>
#include <cstdint>

// Problem constants
#define DM   1024
#define NH   16
#define HD   64
#define DFF  4096
#define BB   2
#define LL   2048
#define MTOT (BB*LL)       // 4096 rows

// ---------------- scratch (static device globals; allocation-free) ----------
__device__ float g_Q[(size_t)NH*BB*LL*HD];
__device__ float g_K[(size_t)NH*BB*LL*HD];
__device__ float g_V[(size_t)NH*BB*LL*HD];
__device__ float g_attn[(size_t)MTOT*DM];
__device__ float g_proj[(size_t)MTOT*DM];
__device__ float g_x[(size_t)MTOT*DM];
__device__ float g_ff1[(size_t)MTOT*DFF];
__device__ float g_ff2[(size_t)MTOT*DM];

// ---------------- mma / ldmatrix helpers -------------------------------------
__device__ __forceinline__ void mma_f16(float* d, const uint32_t* a, const uint32_t* b) {
    asm volatile(
        "mma.sync.aligned.m16n8k16.row.col.f32.f16.f16.f32 "
        "{%0,%1,%2,%3}, {%4,%5,%6,%7}, {%8,%9}, {%0,%1,%2,%3};"
        : "+f"(d[0]), "+f"(d[1]), "+f"(d[2]), "+f"(d[3])
        : "r"(a[0]), "r"(a[1]), "r"(a[2]), "r"(a[3]), "r"(b[0]), "r"(b[1]));
}
__device__ __forceinline__ void ldm_x4(uint32_t& r0, uint32_t& r1, uint32_t& r2, uint32_t& r3,
                                       uint32_t addr) {
    asm volatile("ldmatrix.sync.aligned.m8n8.x4.shared.b16 {%0,%1,%2,%3}, [%4];"
                 : "=r"(r0), "=r"(r1), "=r"(r2), "=r"(r3) : "r"(addr));
}
__device__ __forceinline__ void ldm_x2t(uint32_t& r0, uint32_t& r1, uint32_t addr) {
    asm volatile("ldmatrix.sync.aligned.m8n8.x2.trans.shared.b16 {%0,%1}, [%2];"
                 : "=r"(r0), "=r"(r1) : "r"(addr));
}
__device__ __forceinline__ uint32_t h2u(float x, float y) {
    __half2 h = __float22half2_rn(make_float2(x, y));
    return *(uint32_t*)&h;
}

// ---------------- warp-mma FP16 GEMM: C[M,N] = A[M,K] @ B[K,N] + bias --------
// B used in native [K][N] layout (dataset [in,out] weights) - no transpose.
// EPI 0: plain   EPI 1: exact GELU   EPI 2: split-heads [b*16+h][l][hd]
// 256 threads = 8 warps in 4(m) x 2(n); each warp: 32x64 (2 x 8 m16n8k16 atoms).
#define KC 32                      // K chunk
#define AS_STRIDE 40               // halves per As row (80B: x5 mod 8 -> conflict-free ldmatrix)
#define BS_STRIDE 136              // halves per Bs row (272B: x17 mod 8 -> conflict-free)

template<int EPI>
__global__ __launch_bounds__(256)
void wm_gemm(const float* __restrict__ A, const float* __restrict__ B,
             const float* __restrict__ bias, float* __restrict__ C,
             int M, int N, int K)
{
    __shared__ __align__(16) uint16_t As[128][AS_STRIDE];  // [m][k] fp16
    __shared__ __align__(16) uint16_t Bs[KC][BS_STRIDE];   // [k][n] fp16

    const int tid  = threadIdx.x;
    const int wid  = tid >> 5;
    const int lane = tid & 31;
    const int lg   = lane & 3;          // threadID_in_group
    const int grp  = lane >> 2;         // groupID
    const int n0 = blockIdx.x * 128;
    const int m0 = blockIdx.y * 128;
    const int wm = (wid & 3) * 32;      // warp m offset
    const int wn = (wid >> 2) * 64;     // warp n offset

    // staging indices
    const int arow = tid >> 1, ahalf = (tid & 1) * 16;
    const float* Ap = A + (size_t)(m0 + arow) * K + ahalf;
    const int brow = tid >> 5, bcol = lane * 4;

    // ldmatrix per-thread base addresses
    const uint32_t As_base = (uint32_t)__cvta_generic_to_shared(&As[0][0]);
    const uint32_t Bs_base = (uint32_t)__cvta_generic_to_shared(&Bs[0][0]);
    // A: lanes 0-15 -> rows m0..m15 (k lo), lanes 16-31 -> rows m0..m15 (k hi)
    const uint32_t a_addr0 = As_base +
        (((wm + (lane & 15)) * AS_STRIDE) + ((lane >> 4) * 8)) * 2;
    // B: lanes 0-15 -> rows k0..k15 at col wn
    const uint32_t b_addr0 = Bs_base + (((lane & 15) * BS_STRIDE) + wn) * 2;

    float d[2][8][4];
    #pragma unroll
    for (int i = 0; i < 2; i++)
        #pragma unroll
        for (int j = 0; j < 8; j++)
            #pragma unroll
            for (int q = 0; q < 4; q++) d[i][j][q] = 0.f;

    for (int k0 = 0; k0 < K; k0 += KC) {
        // ---- stage A[m0:128][k0:32] -> As[m][k] fp16 ----
        {
            uint32_t h[8];
            #pragma unroll
            for (int i = 0; i < 4; i++) {
                float4 v = *(const float4*)(Ap + k0 + i * 4);
                h[i * 2 + 0] = h2u(v.x, v.y);
                h[i * 2 + 1] = h2u(v.z, v.w);
            }
            uint4* dst = (uint4*)&As[arow][ahalf];
            dst[0] = make_uint4(h[0], h[1], h[2], h[3]);
            dst[1] = make_uint4(h[4], h[5], h[6], h[7]);
        }
        // ---- stage B[k0:32][n0:128] -> Bs[k][n] fp16 ----
        #pragma unroll
        for (int p = 0; p < 4; p++) {
            int kk = brow + p * 8;
            float4 v = *(const float4*)(B + (size_t)(k0 + kk) * N + n0 + bcol);
            uint2* dst = (uint2*)&Bs[kk][bcol];
            *dst = make_uint2(h2u(v.x, v.y), h2u(v.z, v.w));
        }
        __syncthreads();

        // ---- 2 k16-steps of mma ----
        #pragma unroll
        for (int ks = 0; ks < 2; ks++) {
            uint32_t a[2][4], b[8][2];
            #pragma unroll
            for (int i = 0; i < 2; i++)
                ldm_x4(a[i][0], a[i][1], a[i][2], a[i][3],
                       a_addr0 + (i * 16 * AS_STRIDE + ks * 16) * 2);
            #pragma unroll
            for (int j = 0; j < 8; j++)
                ldm_x2t(b[j][0], b[j][1],
                        b_addr0 + (ks * 16 * BS_STRIDE + j * 8) * 2);
            #pragma unroll
            for (int i = 0; i < 2; i++)
                #pragma unroll
                for (int j = 0; j < 8; j++)
                    mma_f16(d[i][j], a[i], b[j]);
        }
        __syncthreads();
    }

    // ---- epilogue (same accumulator layout as tf32 m16n8) ----
    #pragma unroll
    for (int i = 0; i < 2; i++) {
        const int r0 = m0 + wm + i * 16 + grp;
        #pragma unroll
        for (int j = 0; j < 8; j++) {
            const int c = n0 + wn + j * 8 + lg * 2;
            float2 v0, v1;
            v0.x = d[i][j][0] + bias[c];
            v0.y = d[i][j][1] + bias[c + 1];
            v1.x = d[i][j][2] + bias[c];
            v1.y = d[i][j][3] + bias[c + 1];
            if (EPI == 1) {
                v0.x *= normcdff(v0.x); v0.y *= normcdff(v0.y);
                v1.x *= normcdff(v1.x); v1.y *= normcdff(v1.y);
            }
            if (EPI == 2) {
                const int h = c >> 6, hd = c & 63;
                const int b0_ = r0 >> 11, l0 = r0 & 2047;
                const int r1 = r0 + 8;
                const int b1_ = r1 >> 11, l1 = r1 & 2047;
                *(float2*)(C + ((size_t)((b0_ << 4) + h) * LL + l0) * HD + hd) = v0;
                *(float2*)(C + ((size_t)((b1_ << 4) + h) * LL + l1) * HD + hd) = v1;
            } else {
                *(float2*)(C + (size_t)r0 * N + c) = v0;
                *(float2*)(C + (size_t)(r0 + 8) * N + c) = v1;
            }
        }
    }
}

// ---------------- flash attention (fp32, online softmax) --------------------
__global__ __launch_bounds__(64)
void flash_k(const float* __restrict__ Q, const float* __restrict__ K,
             const float* __restrict__ V, float* __restrict__ O)
{
    __shared__ float4 Ks[64 * 16];
    __shared__ float4 Vs[64 * 16];

    const int t  = threadIdx.x;
    const int bh = blockIdx.y;
    const int q  = blockIdx.x * 64 + t;

    const float4* Qr = (const float4*)(Q + ((size_t)bh * LL + q) * HD);
    float4 qr[16];
    #pragma unroll
    for (int i = 0; i < 16; i++) {
        qr[i] = Qr[i];
        qr[i].x *= 0.125f; qr[i].y *= 0.125f;
        qr[i].z *= 0.125f; qr[i].w *= 0.125f;
    }

    float m = -1e30f, l = 0.f;
    float4 ar[16];
    #pragma unroll
    for (int i = 0; i < 16; i++) ar[i] = make_float4(0.f, 0.f, 0.f, 0.f);

    const float4* Kb = (const float4*)(K + (size_t)bh * LL * HD);
    const float4* Vb = (const float4*)(V + (size_t)bh * LL * HD);

    for (int kt = 0; kt < LL / 64; kt++) {
        const float4* Kt = Kb + kt * 64 * 16;
        const float4* Vt = Vb + kt * 64 * 16;
        for (int i = t; i < 1024; i += 64) { Ks[i] = Kt[i]; Vs[i] = Vt[i]; }
        __syncthreads();

        for (int j = 0; j < 64; j++) {
            const float4* kr = &Ks[j * 16];
            float s = 0.f;
            #pragma unroll
            for (int kk = 0; kk < 16; kk++) {
                float4 kv = kr[kk];
                s = fmaf(qr[kk].x, kv.x, s);
                s = fmaf(qr[kk].y, kv.y, s);
                s = fmaf(qr[kk].z, kv.z, s);
                s = fmaf(qr[kk].w, kv.w, s);
            }
            if (s > m) {
                float f = __expf(m - s);
                m = s; l *= f;
                #pragma unroll
                for (int kk = 0; kk < 16; kk++) {
                    ar[kk].x *= f; ar[kk].y *= f; ar[kk].z *= f; ar[kk].w *= f;
                }
            }
            float p = __expf(s - m);
            l += p;
            const float4* vr = &Vs[j * 16];
            #pragma unroll
            for (int kk = 0; kk < 16; kk++) {
                float4 vv = vr[kk];
                ar[kk].x = fmaf(p, vv.x, ar[kk].x);
                ar[kk].y = fmaf(p, vv.y, ar[kk].y);
                ar[kk].z = fmaf(p, vv.z, ar[kk].z);
                ar[kk].w = fmaf(p, vv.w, ar[kk].w);
            }
        }
        __syncthreads();
    }

    const float inv = 1.f / l;
    const int b = bh >> 4, h = bh & 15;
    float4* Or = (float4*)(O + ((size_t)(b * LL + q)) * DM + h * HD);
    #pragma unroll
    for (int kk = 0; kk < 16; kk++) {
        float4 v = ar[kk];
        v.x *= inv; v.y *= inv; v.z *= inv; v.w *= inv;
        Or[kk] = v;
    }
}

// ---------------- fused residual add + LayerNorm ----------------------------
__global__ __launch_bounds__(256)
void add_ln_k(const float* __restrict__ A, const float* __restrict__ B,
              const float* __restrict__ gamma, const float* __restrict__ beta,
              float* __restrict__ out)
{
    const int row = blockIdx.x, t = threadIdx.x;
    const float4* a = (const float4*)(A + (size_t)row * DM);
    const float4* b = (const float4*)(B + (size_t)row * DM);
    float4 v = a[t], w = b[t];
    v.x += w.x; v.y += w.y; v.z += w.z; v.w += w.w;

    float s = v.x + v.y + v.z + v.w;
    float q = v.x * v.x + v.y * v.y + v.z * v.z + v.w * v.w;
    #pragma unroll
    for (int o = 16; o > 0; o >>= 1) {
        s += __shfl_xor_sync(0xffffffffu, s, o);
        q += __shfl_xor_sync(0xffffffffu, q, o);
    }
    __shared__ float ss[8], sq[8];
    const int wid = t >> 5, lane = t & 31;
    if (lane == 0) { ss[wid] = s; sq[wid] = q; }
    __syncthreads();
    s = 0.f; q = 0.f;
    #pragma unroll
    for (int i = 0; i < 8; i++) { s += ss[i]; q += sq[i]; }

    const float mean = s * (1.f / DM);
    const float var  = q * (1.f / DM) - mean * mean;
    const float rstd = rsqrtf(var + 1e-5f);

    const int c = t * 4;
    float4 g  = *(const float4*)(gamma + c);
    float4 be = *(const float4*)(beta + c);
    float4 o;
    o.x = (v.x - mean) * rstd * g.x + be.x;
    o.y = (v.y - mean) * rstd * g.y + be.y;
    o.z = (v.z - mean) * rstd * g.z + be.z;
    o.w = (v.w - mean) * rstd * g.w + be.w;
    ((float4*)(out + (size_t)row * DM))[t] = o;
}

// ---------------- launcher ---------------------------------------------------
extern "C" void kernel_launch(void* const* d_in, const int* in_sizes, int n_in,
                              void* d_out, int out_size)
{
    const float* src = (const float*)d_in[0];
    const float* Wq  = (const float*)d_in[1];  const float* bq = (const float*)d_in[2];
    const float* Wk  = (const float*)d_in[3];  const float* bk = (const float*)d_in[4];
    const float* Wv  = (const float*)d_in[5];  const float* bv = (const float*)d_in[6];
    const float* Wo  = (const float*)d_in[7];  const float* bo = (const float*)d_in[8];
    const float* W1  = (const float*)d_in[9];  const float* b1 = (const float*)d_in[10];
    const float* W2  = (const float*)d_in[11]; const float* b2 = (const float*)d_in[12];
    const float* gamma1 = (const float*)d_in[13]; const float* beta1 = (const float*)d_in[14];
    const float* gamma2 = (const float*)d_in[15]; const float* beta2 = (const float*)d_in[16];
    float* out = (float*)d_out;

    float *Qb, *Kb, *Vb, *attn, *proj, *x, *ff1, *ff2;
    cudaGetSymbolAddress((void**)&Qb,   g_Q);
    cudaGetSymbolAddress((void**)&Kb,   g_K);
    cudaGetSymbolAddress((void**)&Vb,   g_V);
    cudaGetSymbolAddress((void**)&attn, g_attn);
    cudaGetSymbolAddress((void**)&proj, g_proj);
    cudaGetSymbolAddress((void**)&x,    g_x);
    cudaGetSymbolAddress((void**)&ff1,  g_ff1);
    cudaGetSymbolAddress((void**)&ff2,  g_ff2);

    // QKV projections (split-heads epilogue); weights used natively [K][N]
    wm_gemm<2><<<dim3(DM / 128, MTOT / 128), 256>>>(src, Wq, bq, Qb, MTOT, DM, DM);
    wm_gemm<2><<<dim3(DM / 128, MTOT / 128), 256>>>(src, Wk, bk, Kb, MTOT, DM, DM);
    wm_gemm<2><<<dim3(DM / 128, MTOT / 128), 256>>>(src, Wv, bv, Vb, MTOT, DM, DM);

    // attention (merged-head output)
    flash_k<<<dim3(LL / 64, BB * NH), 64>>>(Qb, Kb, Vb, attn);

    // output projection
    wm_gemm<0><<<dim3(DM / 128, MTOT / 128), 256>>>(attn, Wo, bo, proj, MTOT, DM, DM);

    // x = LN(src + attn_proj)
    add_ln_k<<<MTOT, 256>>>(src, proj, gamma1, beta1, x);

    // FF
    wm_gemm<1><<<dim3(DFF / 128, MTOT / 128), 256>>>(x, W1, b1, ff1, MTOT, DFF, DM);
    wm_gemm<0><<<dim3(DM / 128, MTOT / 128), 256>>>(ff1, W2, b2, ff2, MTOT, DM, DFF);

    // out = LN(x + ff)
    add_ln_k<<<MTOT, 256>>>(x, ff2, gamma2, beta2, out);
}

// round 5
// speedup vs baseline: 3.9680x; 2.1393x over previous
#include <cuda_runtime.h>
#include <cuda_fp16.h>
#include <math.h>
#include <cstdint>

// Problem constants
#define DM   1024
#define NH   16
#define HD   64
#define DFF  4096
#define BB   2
#define LL   2048
#define MTOT (BB*LL)       // 4096 rows

// ---------------- scratch (static device globals; allocation-free) ----------
__device__ float g_Q[(size_t)NH*BB*LL*HD];
__device__ float g_K[(size_t)NH*BB*LL*HD];
__device__ float g_V[(size_t)NH*BB*LL*HD];
__device__ float g_attn[(size_t)MTOT*DM];
__device__ float g_proj[(size_t)MTOT*DM];
__device__ float g_x[(size_t)MTOT*DM];
__device__ float g_ff1[(size_t)MTOT*DFF];
__device__ float g_ff2[(size_t)MTOT*DM];

// ---------------- mma / ldmatrix helpers -------------------------------------
__device__ __forceinline__ void mma_f16(float* d, const uint32_t* a, const uint32_t* b) {
    asm volatile(
        "mma.sync.aligned.m16n8k16.row.col.f32.f16.f16.f32 "
        "{%0,%1,%2,%3}, {%4,%5,%6,%7}, {%8,%9}, {%0,%1,%2,%3};"
        : "+f"(d[0]), "+f"(d[1]), "+f"(d[2]), "+f"(d[3])
        : "r"(a[0]), "r"(a[1]), "r"(a[2]), "r"(a[3]), "r"(b[0]), "r"(b[1]));
}
__device__ __forceinline__ void ldm_x4(uint32_t& r0, uint32_t& r1, uint32_t& r2, uint32_t& r3,
                                       uint32_t addr) {
    asm volatile("ldmatrix.sync.aligned.m8n8.x4.shared.b16 {%0,%1,%2,%3}, [%4];"
                 : "=r"(r0), "=r"(r1), "=r"(r2), "=r"(r3) : "r"(addr));
}
__device__ __forceinline__ void ldm_x2t(uint32_t& r0, uint32_t& r1, uint32_t addr) {
    asm volatile("ldmatrix.sync.aligned.m8n8.x2.trans.shared.b16 {%0,%1}, [%2];"
                 : "=r"(r0), "=r"(r1) : "r"(addr));
}
__device__ __forceinline__ uint32_t h2u(float x, float y) {
    __half2 h = __float22half2_rn(make_float2(x, y));
    return *(uint32_t*)&h;
}

// ---------------- warp-mma FP16 GEMM: C[M,N] = A[M,K] @ B[K,N] + bias --------
#define KC 32
#define AS_STRIDE 40
#define BS_STRIDE 136

template<int EPI>
__global__ __launch_bounds__(256)
void wm_gemm(const float* __restrict__ A, const float* __restrict__ B,
             const float* __restrict__ bias, float* __restrict__ C,
             int M, int N, int K)
{
    __shared__ __align__(16) uint16_t As[128][AS_STRIDE];
    __shared__ __align__(16) uint16_t Bs[KC][BS_STRIDE];

    const int tid  = threadIdx.x;
    const int wid  = tid >> 5;
    const int lane = tid & 31;
    const int lg   = lane & 3;
    const int grp  = lane >> 2;
    const int n0 = blockIdx.x * 128;
    const int m0 = blockIdx.y * 128;
    const int wm = (wid & 3) * 32;
    const int wn = (wid >> 2) * 64;

    const int arow = tid >> 1, ahalf = (tid & 1) * 16;
    const float* Ap = A + (size_t)(m0 + arow) * K + ahalf;
    const int brow = tid >> 5, bcol = lane * 4;

    const uint32_t As_base = (uint32_t)__cvta_generic_to_shared(&As[0][0]);
    const uint32_t Bs_base = (uint32_t)__cvta_generic_to_shared(&Bs[0][0]);
    const uint32_t a_addr0 = As_base +
        (((wm + (lane & 15)) * AS_STRIDE) + ((lane >> 4) * 8)) * 2;
    const uint32_t b_addr0 = Bs_base + (((lane & 15) * BS_STRIDE) + wn) * 2;

    float d[2][8][4];
    #pragma unroll
    for (int i = 0; i < 2; i++)
        #pragma unroll
        for (int j = 0; j < 8; j++)
            #pragma unroll
            for (int q = 0; q < 4; q++) d[i][j][q] = 0.f;

    for (int k0 = 0; k0 < K; k0 += KC) {
        {
            uint32_t h[8];
            #pragma unroll
            for (int i = 0; i < 4; i++) {
                float4 v = *(const float4*)(Ap + k0 + i * 4);
                h[i * 2 + 0] = h2u(v.x, v.y);
                h[i * 2 + 1] = h2u(v.z, v.w);
            }
            uint4* dst = (uint4*)&As[arow][ahalf];
            dst[0] = make_uint4(h[0], h[1], h[2], h[3]);
            dst[1] = make_uint4(h[4], h[5], h[6], h[7]);
        }
        #pragma unroll
        for (int p = 0; p < 4; p++) {
            int kk = brow + p * 8;
            float4 v = *(const float4*)(B + (size_t)(k0 + kk) * N + n0 + bcol);
            uint2* dst = (uint2*)&Bs[kk][bcol];
            *dst = make_uint2(h2u(v.x, v.y), h2u(v.z, v.w));
        }
        __syncthreads();

        #pragma unroll
        for (int ks = 0; ks < 2; ks++) {
            uint32_t a[2][4], b[8][2];
            #pragma unroll
            for (int i = 0; i < 2; i++)
                ldm_x4(a[i][0], a[i][1], a[i][2], a[i][3],
                       a_addr0 + (i * 16 * AS_STRIDE + ks * 16) * 2);
            #pragma unroll
            for (int j = 0; j < 8; j++)
                ldm_x2t(b[j][0], b[j][1],
                        b_addr0 + (ks * 16 * BS_STRIDE + j * 8) * 2);
            #pragma unroll
            for (int i = 0; i < 2; i++)
                #pragma unroll
                for (int j = 0; j < 8; j++)
                    mma_f16(d[i][j], a[i], b[j]);
        }
        __syncthreads();
    }

    #pragma unroll
    for (int i = 0; i < 2; i++) {
        const int r0 = m0 + wm + i * 16 + grp;
        #pragma unroll
        for (int j = 0; j < 8; j++) {
            const int c = n0 + wn + j * 8 + lg * 2;
            float2 v0, v1;
            v0.x = d[i][j][0] + bias[c];
            v0.y = d[i][j][1] + bias[c + 1];
            v1.x = d[i][j][2] + bias[c];
            v1.y = d[i][j][3] + bias[c + 1];
            if (EPI == 1) {
                v0.x *= normcdff(v0.x); v0.y *= normcdff(v0.y);
                v1.x *= normcdff(v1.x); v1.y *= normcdff(v1.y);
            }
            if (EPI == 2) {
                const int h = c >> 6, hd = c & 63;
                const int b0_ = r0 >> 11, l0 = r0 & 2047;
                const int r1 = r0 + 8;
                const int b1_ = r1 >> 11, l1 = r1 & 2047;
                *(float2*)(C + ((size_t)((b0_ << 4) + h) * LL + l0) * HD + hd) = v0;
                *(float2*)(C + ((size_t)((b1_ << 4) + h) * LL + l1) * HD + hd) = v1;
            } else {
                *(float2*)(C + (size_t)r0 * N + c) = v0;
                *(float2*)(C + (size_t)(r0 + 8) * N + c) = v1;
            }
        }
    }
}

// ---------------- tensor-core flash attention (fp16 mma, FA2) ----------------
// grid (L/64, B*H), 128 threads = 4 warps; warp w owns q rows [w*16, w*16+16).
// 64-key tiles; online softmax in registers; P reused as mma A operand.
#define FS 72   // smem row stride in halves (144B -> conflict-free ldmatrix)

__global__ __launch_bounds__(128)
void flash_mma(const float* __restrict__ Q, const float* __restrict__ Kg,
               const float* __restrict__ Vg, float* __restrict__ O)
{
    __shared__ __align__(16) uint16_t Qs[64][FS];
    __shared__ __align__(16) uint16_t Ks[64][FS];
    __shared__ __align__(16) uint16_t Vs[64][FS];

    const int tid  = threadIdx.x;
    const int wid  = tid >> 5;
    const int lane = tid & 31;
    const int grp  = lane >> 2;
    const int lg   = lane & 3;
    const int bh   = blockIdx.y;
    const int q0   = blockIdx.x * 64;

    const int lrow = tid >> 1, lhalf = (tid & 1) * 32;

    // ---- stage Q tile (pre-scaled by 1/sqrt(64)) ----
    {
        const float4* src = (const float4*)(Q + ((size_t)bh * LL + q0 + lrow) * HD + lhalf);
        uint32_t h[16];
        #pragma unroll
        for (int i = 0; i < 8; i++) {
            float4 v = src[i];
            h[2 * i]     = h2u(v.x * 0.125f, v.y * 0.125f);
            h[2 * i + 1] = h2u(v.z * 0.125f, v.w * 0.125f);
        }
        uint4* dst = (uint4*)&Qs[lrow][lhalf];
        dst[0] = make_uint4(h[0], h[1], h[2], h[3]);
        dst[1] = make_uint4(h[4], h[5], h[6], h[7]);
        dst[2] = make_uint4(h[8], h[9], h[10], h[11]);
        dst[3] = make_uint4(h[12], h[13], h[14], h[15]);
    }
    __syncthreads();

    // ---- Q a-fragments, resident for the whole kernel ----
    uint32_t qa[4][4];
    {
        const uint32_t Qb = (uint32_t)__cvta_generic_to_shared(&Qs[0][0]);
        const uint32_t qaddr = Qb + (((wid * 16 + (lane & 15)) * FS) + (lane >> 4) * 8) * 2;
        #pragma unroll
        for (int ks = 0; ks < 4; ks++)
            ldm_x4(qa[ks][0], qa[ks][1], qa[ks][2], qa[ks][3], qaddr + ks * 16 * 2);
    }

    // K b-frag address: x4 covers n16 x k16 (2 n-atoms)
    const uint32_t Kb_s = (uint32_t)__cvta_generic_to_shared(&Ks[0][0]);
    const uint32_t kaddr = Kb_s +
        ((((lane >> 4) * 8 + (lane & 7)) * FS) + ((lane >> 3) & 1) * 8) * 2;
    // V b-frag address: x2.trans, rows = key (k), cols = hd (n)
    const uint32_t Vb_s = (uint32_t)__cvta_generic_to_shared(&Vs[0][0]);
    const uint32_t vaddr = Vb_s + ((lane & 15) * FS) * 2;

    float m0 = -1e30f, m1 = -1e30f, l0 = 0.f, l1 = 0.f;
    float oacc[8][4];
    #pragma unroll
    for (int j = 0; j < 8; j++)
        #pragma unroll
        for (int q = 0; q < 4; q++) oacc[j][q] = 0.f;

    const float* Kp = Kg + (size_t)bh * LL * HD;
    const float* Vp = Vg + (size_t)bh * LL * HD;

    for (int kt = 0; kt < LL / 64; kt++) {
        // ---- stage K,V tiles (fp32 -> fp16) ----
        {
            const float4* ksrc = (const float4*)(Kp + (size_t)(kt * 64 + lrow) * HD + lhalf);
            const float4* vsrc = (const float4*)(Vp + (size_t)(kt * 64 + lrow) * HD + lhalf);
            uint32_t hk[16], hv[16];
            #pragma unroll
            for (int i = 0; i < 8; i++) {
                float4 kv = ksrc[i];
                float4 vv = vsrc[i];
                hk[2 * i]     = h2u(kv.x, kv.y);
                hk[2 * i + 1] = h2u(kv.z, kv.w);
                hv[2 * i]     = h2u(vv.x, vv.y);
                hv[2 * i + 1] = h2u(vv.z, vv.w);
            }
            uint4* kd = (uint4*)&Ks[lrow][lhalf];
            uint4* vd = (uint4*)&Vs[lrow][lhalf];
            kd[0] = make_uint4(hk[0], hk[1], hk[2], hk[3]);
            kd[1] = make_uint4(hk[4], hk[5], hk[6], hk[7]);
            kd[2] = make_uint4(hk[8], hk[9], hk[10], hk[11]);
            kd[3] = make_uint4(hk[12], hk[13], hk[14], hk[15]);
            vd[0] = make_uint4(hv[0], hv[1], hv[2], hv[3]);
            vd[1] = make_uint4(hv[4], hv[5], hv[6], hv[7]);
            vd[2] = make_uint4(hv[8], hv[9], hv[10], hv[11]);
            vd[3] = make_uint4(hv[12], hv[13], hv[14], hv[15]);
        }
        __syncthreads();

        // ---- S = Q @ K^T  (16 x 64 per warp) ----
        float sacc[8][4];
        #pragma unroll
        for (int na = 0; na < 8; na++)
            #pragma unroll
            for (int q = 0; q < 4; q++) sacc[na][q] = 0.f;

        #pragma unroll
        for (int ks = 0; ks < 4; ks++) {
            #pragma unroll
            for (int na2 = 0; na2 < 4; na2++) {
                uint32_t b0, b1, b2, b3;
                ldm_x4(b0, b1, b2, b3, kaddr + (na2 * 16 * FS + ks * 16) * 2);
                uint32_t bb0[2] = {b0, b1};
                uint32_t bb1[2] = {b2, b3};
                mma_f16(sacc[na2 * 2], qa[ks], bb0);
                mma_f16(sacc[na2 * 2 + 1], qa[ks], bb1);
            }
        }

        // ---- online softmax (rows grp, grp+8) ----
        float tm0 = -1e30f, tm1 = -1e30f;
        #pragma unroll
        for (int na = 0; na < 8; na++) {
            tm0 = fmaxf(tm0, fmaxf(sacc[na][0], sacc[na][1]));
            tm1 = fmaxf(tm1, fmaxf(sacc[na][2], sacc[na][3]));
        }
        tm0 = fmaxf(tm0, __shfl_xor_sync(0xffffffffu, tm0, 1));
        tm0 = fmaxf(tm0, __shfl_xor_sync(0xffffffffu, tm0, 2));
        tm1 = fmaxf(tm1, __shfl_xor_sync(0xffffffffu, tm1, 1));
        tm1 = fmaxf(tm1, __shfl_xor_sync(0xffffffffu, tm1, 2));
        const float nm0 = fmaxf(m0, tm0), nm1 = fmaxf(m1, tm1);
        const float f0 = __expf(m0 - nm0), f1 = __expf(m1 - nm1);
        m0 = nm0; m1 = nm1;

        float s0 = 0.f, s1 = 0.f;
        uint32_t pa[4][4];
        #pragma unroll
        for (int na = 0; na < 8; na++) {
            float p0 = __expf(sacc[na][0] - nm0);
            float p1 = __expf(sacc[na][1] - nm0);
            float p2 = __expf(sacc[na][2] - nm1);
            float p3 = __expf(sacc[na][3] - nm1);
            s0 += p0 + p1; s1 += p2 + p3;
            pa[na >> 1][(na & 1) * 2 + 0] = h2u(p0, p1);
            pa[na >> 1][(na & 1) * 2 + 1] = h2u(p2, p3);
        }
        s0 += __shfl_xor_sync(0xffffffffu, s0, 1);
        s0 += __shfl_xor_sync(0xffffffffu, s0, 2);
        s1 += __shfl_xor_sync(0xffffffffu, s1, 1);
        s1 += __shfl_xor_sync(0xffffffffu, s1, 2);
        l0 = l0 * f0 + s0;
        l1 = l1 * f1 + s1;
        #pragma unroll
        for (int j = 0; j < 8; j++) {
            oacc[j][0] *= f0; oacc[j][1] *= f0;
            oacc[j][2] *= f1; oacc[j][3] *= f1;
        }

        // ---- O += P @ V ----
        #pragma unroll
        for (int ks = 0; ks < 4; ks++) {
            #pragma unroll
            for (int j = 0; j < 8; j++) {
                uint32_t b0, b1;
                ldm_x2t(b0, b1, vaddr + (ks * 16 * FS + j * 8) * 2);
                uint32_t bb[2] = {b0, b1};
                mma_f16(oacc[j], pa[ks], bb);
            }
        }
        __syncthreads();
    }

    // ---- write merged-head output ----
    const float inv0 = 1.f / l0, inv1 = 1.f / l1;
    const int b = bh >> 4, h = bh & 15;
    const int r0 = q0 + wid * 16 + grp;
    float* O0 = O + ((size_t)(b * LL + r0)) * DM + h * HD;
    float* O1 = O0 + (size_t)8 * DM;
    #pragma unroll
    for (int j = 0; j < 8; j++) {
        float2 v0 = make_float2(oacc[j][0] * inv0, oacc[j][1] * inv0);
        float2 v1 = make_float2(oacc[j][2] * inv1, oacc[j][3] * inv1);
        *(float2*)(O0 + j * 8 + 2 * lg) = v0;
        *(float2*)(O1 + j * 8 + 2 * lg) = v1;
    }
}

// ---------------- fused residual add + LayerNorm ----------------------------
__global__ __launch_bounds__(256)
void add_ln_k(const float* __restrict__ A, const float* __restrict__ B,
              const float* __restrict__ gamma, const float* __restrict__ beta,
              float* __restrict__ out)
{
    const int row = blockIdx.x, t = threadIdx.x;
    const float4* a = (const float4*)(A + (size_t)row * DM);
    const float4* b = (const float4*)(B + (size_t)row * DM);
    float4 v = a[t], w = b[t];
    v.x += w.x; v.y += w.y; v.z += w.z; v.w += w.w;

    float s = v.x + v.y + v.z + v.w;
    float q = v.x * v.x + v.y * v.y + v.z * v.z + v.w * v.w;
    #pragma unroll
    for (int o = 16; o > 0; o >>= 1) {
        s += __shfl_xor_sync(0xffffffffu, s, o);
        q += __shfl_xor_sync(0xffffffffu, q, o);
    }
    __shared__ float ss[8], sq[8];
    const int wid = t >> 5, lane = t & 31;
    if (lane == 0) { ss[wid] = s; sq[wid] = q; }
    __syncthreads();
    s = 0.f; q = 0.f;
    #pragma unroll
    for (int i = 0; i < 8; i++) { s += ss[i]; q += sq[i]; }

    const float mean = s * (1.f / DM);
    const float var  = q * (1.f / DM) - mean * mean;
    const float rstd = rsqrtf(var + 1e-5f);

    const int c = t * 4;
    float4 g  = *(const float4*)(gamma + c);
    float4 be = *(const float4*)(beta + c);
    float4 o;
    o.x = (v.x - mean) * rstd * g.x + be.x;
    o.y = (v.y - mean) * rstd * g.y + be.y;
    o.z = (v.z - mean) * rstd * g.z + be.z;
    o.w = (v.w - mean) * rstd * g.w + be.w;
    ((float4*)(out + (size_t)row * DM))[t] = o;
}

// ---------------- launcher ---------------------------------------------------
extern "C" void kernel_launch(void* const* d_in, const int* in_sizes, int n_in,
                              void* d_out, int out_size)
{
    const float* src = (const float*)d_in[0];
    const float* Wq  = (const float*)d_in[1];  const float* bq = (const float*)d_in[2];
    const float* Wk  = (const float*)d_in[3];  const float* bk = (const float*)d_in[4];
    const float* Wv  = (const float*)d_in[5];  const float* bv = (const float*)d_in[6];
    const float* Wo  = (const float*)d_in[7];  const float* bo = (const float*)d_in[8];
    const float* W1  = (const float*)d_in[9];  const float* b1 = (const float*)d_in[10];
    const float* W2  = (const float*)d_in[11]; const float* b2 = (const float*)d_in[12];
    const float* gamma1 = (const float*)d_in[13]; const float* beta1 = (const float*)d_in[14];
    const float* gamma2 = (const float*)d_in[15]; const float* beta2 = (const float*)d_in[16];
    float* out = (float*)d_out;

    float *Qb, *Kb, *Vb, *attn, *proj, *x, *ff1, *ff2;
    cudaGetSymbolAddress((void**)&Qb,   g_Q);
    cudaGetSymbolAddress((void**)&Kb,   g_K);
    cudaGetSymbolAddress((void**)&Vb,   g_V);
    cudaGetSymbolAddress((void**)&attn, g_attn);
    cudaGetSymbolAddress((void**)&proj, g_proj);
    cudaGetSymbolAddress((void**)&x,    g_x);
    cudaGetSymbolAddress((void**)&ff1,  g_ff1);
    cudaGetSymbolAddress((void**)&ff2,  g_ff2);

    // QKV projections (split-heads epilogue); weights used natively [K][N]
    wm_gemm<2><<<dim3(DM / 128, MTOT / 128), 256>>>(src, Wq, bq, Qb, MTOT, DM, DM);
    wm_gemm<2><<<dim3(DM / 128, MTOT / 128), 256>>>(src, Wk, bk, Kb, MTOT, DM, DM);
    wm_gemm<2><<<dim3(DM / 128, MTOT / 128), 256>>>(src, Wv, bv, Vb, MTOT, DM, DM);

    // tensor-core flash attention (merged-head output)
    flash_mma<<<dim3(LL / 64, BB * NH), 128>>>(Qb, Kb, Vb, attn);

    // output projection
    wm_gemm<0><<<dim3(DM / 128, MTOT / 128), 256>>>(attn, Wo, bo, proj, MTOT, DM, DM);

    // x = LN(src + attn_proj)
    add_ln_k<<<MTOT, 256>>>(src, proj, gamma1, beta1, x);

    // FF
    wm_gemm<1><<<dim3(DFF / 128, MTOT / 128), 256>>>(x, W1, b1, ff1, MTOT, DFF, DM);
    wm_gemm<0><<<dim3(DM / 128, MTOT / 128), 256>>>(ff1, W2, b2, ff2, MTOT, DM, DFF);

    // out = LN(x + ff)
    add_ln_k<<<MTOT, 256>>>(x, ff2, gamma2, beta2, out);
}

// round 6
// speedup vs baseline: 6.6374x; 1.6727x over previous
#include <cuda_runtime.h>
#include <cuda_fp16.h>
#include <math.h>
#include <cstdint>

#define DM   1024
#define NH   16
#define HD   64
#define DFF  4096
#define BB   2
#define LL   2048
#define MTOT (BB*LL)

// ---------------- scratch (static device globals; allocation-free) ----------
__device__ __half g_srch[(size_t)MTOT*DM];
__device__ __half g_Wqh[(size_t)DM*DM];
__device__ __half g_Wkh[(size_t)DM*DM];
__device__ __half g_Wvh[(size_t)DM*DM];
__device__ __half g_Woh[(size_t)DM*DM];
__device__ __half g_W1h[(size_t)DM*DFF];
__device__ __half g_W2h[(size_t)DFF*DM];
__device__ __half g_Qh[(size_t)NH*BB*LL*HD];
__device__ __half g_Kh[(size_t)NH*BB*LL*HD];
__device__ __half g_Vh[(size_t)NH*BB*LL*HD];
__device__ __half g_attnh[(size_t)MTOT*DM];
__device__ float  g_proj[(size_t)MTOT*DM];
__device__ float  g_x[(size_t)MTOT*DM];
__device__ __half g_xh[(size_t)MTOT*DM];
__device__ __half g_ff1h[(size_t)MTOT*DFF];
__device__ float  g_ff2[(size_t)MTOT*DM];

// ---------------- helpers ------------------------------------------------------
__device__ __forceinline__ void mma_f16(float* d, const uint32_t* a, const uint32_t* b) {
    asm volatile(
        "mma.sync.aligned.m16n8k16.row.col.f32.f16.f16.f32 "
        "{%0,%1,%2,%3}, {%4,%5,%6,%7}, {%8,%9}, {%0,%1,%2,%3};"
        : "+f"(d[0]), "+f"(d[1]), "+f"(d[2]), "+f"(d[3])
        : "r"(a[0]), "r"(a[1]), "r"(a[2]), "r"(a[3]), "r"(b[0]), "r"(b[1]));
}
__device__ __forceinline__ void ldm_x4(uint32_t& r0, uint32_t& r1, uint32_t& r2, uint32_t& r3,
                                       uint32_t addr) {
    asm volatile("ldmatrix.sync.aligned.m8n8.x4.shared.b16 {%0,%1,%2,%3}, [%4];"
                 : "=r"(r0), "=r"(r1), "=r"(r2), "=r"(r3) : "r"(addr));
}
__device__ __forceinline__ void ldm_x2t(uint32_t& r0, uint32_t& r1, uint32_t addr) {
    asm volatile("ldmatrix.sync.aligned.m8n8.x2.trans.shared.b16 {%0,%1}, [%2];"
                 : "=r"(r0), "=r"(r1) : "r"(addr));
}
__device__ __forceinline__ uint32_t h2u(float x, float y) {
    __half2 h = __float22half2_rn(make_float2(x, y));
    return *(uint32_t*)&h;
}
__device__ __forceinline__ void cp16(uint32_t dst, const void* src) {
    asm volatile("cp.async.cg.shared.global [%0], [%1], 16;" :: "r"(dst), "l"(src));
}
#define CP_COMMIT() asm volatile("cp.async.commit_group;" ::: "memory")
#define CP_WAIT(N)  asm volatile("cp.async.wait_group %0;" :: "n"(N) : "memory")

// ---------------- fp32 -> fp16 convert --------------------------------------
__global__ __launch_bounds__(256)
void f2h_k(const float* __restrict__ in, __half* __restrict__ out, int n)
{
    int i = (blockIdx.x * 256 + threadIdx.x) * 8;
    if (i < n) {
        float4 a = *(const float4*)(in + i);
        float4 b = *(const float4*)(in + i + 4);
        uint4 o;
        o.x = h2u(a.x, a.y); o.y = h2u(a.z, a.w);
        o.z = h2u(b.x, b.y); o.w = h2u(b.z, b.w);
        *(uint4*)(out + i) = o;
    }
}

// ---------------- warp-mma FP16 GEMM, cp.async double-buffered ---------------
// A[M][K] fp16, B[K][N] fp16.  EPI 0: fp32 plain  1: gelu fp16  2: split-head fp16
#define KC 32
#define AS_STRIDE 40               // halves; 80B rows
#define BS_STRIDE 136              // halves; 272B rows
#define ASB (128 * AS_STRIDE * 2)  // bytes per A buffer
#define BSB (KC * BS_STRIDE * 2)   // bytes per B buffer

template<int EPI>
__global__ __launch_bounds__(256)
void wm_gemm(const __half* __restrict__ A, const __half* __restrict__ B,
             const float* __restrict__ bias, void* __restrict__ Cv,
             int M, int N, int K)
{
    __shared__ __align__(16) uint16_t As[2][128][AS_STRIDE];
    __shared__ __align__(16) uint16_t Bs[2][KC][BS_STRIDE];

    const int tid  = threadIdx.x;
    const int wid  = tid >> 5;
    const int lane = tid & 31;
    const int lg   = lane & 3;
    const int grp  = lane >> 2;
    const int n0 = blockIdx.x * 128;
    const int m0 = blockIdx.y * 128;
    const int wm = (wid & 3) * 32;
    const int wn = (wid >> 2) * 64;

    const uint32_t As_base = (uint32_t)__cvta_generic_to_shared(&As[0][0][0]);
    const uint32_t Bs_base = (uint32_t)__cvta_generic_to_shared(&Bs[0][0][0]);

    // staging indices
    const int arow = tid >> 1, acol = (tid & 1) * 16;       // 16 halves each
    const int brow = tid >> 3, bcol = (tid & 7) * 16;       // 16 halves each
    const __half* Ap = A + (size_t)(m0 + arow) * K + acol;
    const __half* Bp = B + (size_t)brow * N + n0 + bcol;
    const uint32_t a_dst = As_base + arow * (AS_STRIDE * 2) + acol * 2;
    const uint32_t b_dst = Bs_base + brow * (BS_STRIDE * 2) + bcol * 2;

    // ldmatrix addresses
    const uint32_t a_addr0 = As_base +
        ((wm + (lane & 15)) * AS_STRIDE + (lane >> 4) * 8) * 2;
    const uint32_t b_addr0 = Bs_base + ((lane & 15) * BS_STRIDE + wn) * 2;

    float d[2][8][4];
    #pragma unroll
    for (int i = 0; i < 2; i++)
        #pragma unroll
        for (int j = 0; j < 8; j++)
            #pragma unroll
            for (int q = 0; q < 4; q++) d[i][j][q] = 0.f;

    const int C_CHUNKS = K >> 5;

    // prefetch chunks 0,1
    #pragma unroll
    for (int pc = 0; pc < 2; pc++) {
        cp16(a_dst + pc * ASB,      Ap + pc * KC);
        cp16(a_dst + pc * ASB + 16, Ap + pc * KC + 8);
        cp16(b_dst + pc * BSB,      Bp + (size_t)pc * KC * N);
        cp16(b_dst + pc * BSB + 16, Bp + (size_t)pc * KC * N + 8);
        CP_COMMIT();
    }

    for (int c = 0; c < C_CHUNKS; c++) {
        const int buf = c & 1;
        CP_WAIT(1);
        __syncthreads();

        #pragma unroll
        for (int ks = 0; ks < 2; ks++) {
            uint32_t a[2][4], b[8][2];
            #pragma unroll
            for (int i = 0; i < 2; i++)
                ldm_x4(a[i][0], a[i][1], a[i][2], a[i][3],
                       a_addr0 + buf * ASB + (i * 16 * AS_STRIDE + ks * 16) * 2);
            #pragma unroll
            for (int j = 0; j < 8; j++)
                ldm_x2t(b[j][0], b[j][1],
                        b_addr0 + buf * BSB + (ks * 16 * BS_STRIDE + j * 8) * 2);
            #pragma unroll
            for (int i = 0; i < 2; i++)
                #pragma unroll
                for (int j = 0; j < 8; j++)
                    mma_f16(d[i][j], a[i], b[j]);
        }
        __syncthreads();
        if (c + 2 < C_CHUNKS) {
            cp16(a_dst + buf * ASB,      Ap + (c + 2) * KC);
            cp16(a_dst + buf * ASB + 16, Ap + (c + 2) * KC + 8);
            cp16(b_dst + buf * BSB,      Bp + (size_t)(c + 2) * KC * N);
            cp16(b_dst + buf * BSB + 16, Bp + (size_t)(c + 2) * KC * N + 8);
        }
        CP_COMMIT();
    }

    // ---- epilogue ----
    #pragma unroll
    for (int i = 0; i < 2; i++) {
        const int r0 = m0 + wm + i * 16 + grp;
        #pragma unroll
        for (int j = 0; j < 8; j++) {
            const int c = n0 + wn + j * 8 + lg * 2;
            float2 v0, v1;
            v0.x = d[i][j][0] + bias[c];
            v0.y = d[i][j][1] + bias[c + 1];
            v1.x = d[i][j][2] + bias[c];
            v1.y = d[i][j][3] + bias[c + 1];
            if (EPI == 0) {
                float* C = (float*)Cv;
                *(float2*)(C + (size_t)r0 * N + c) = v0;
                *(float2*)(C + (size_t)(r0 + 8) * N + c) = v1;
            } else if (EPI == 1) {
                v0.x *= normcdff(v0.x); v0.y *= normcdff(v0.y);
                v1.x *= normcdff(v1.x); v1.y *= normcdff(v1.y);
                __half* C = (__half*)Cv;
                *(uint32_t*)(C + (size_t)r0 * N + c) = h2u(v0.x, v0.y);
                *(uint32_t*)(C + (size_t)(r0 + 8) * N + c) = h2u(v1.x, v1.y);
            } else {
                const int h = c >> 6, hd = c & 63;
                const int b0_ = r0 >> 11, l0 = r0 & 2047;
                const int r1 = r0 + 8;
                const int b1_ = r1 >> 11, l1 = r1 & 2047;
                __half* C = (__half*)Cv;
                *(uint32_t*)(C + ((size_t)((b0_ << 4) + h) * LL + l0) * HD + hd) = h2u(v0.x, v0.y);
                *(uint32_t*)(C + ((size_t)((b1_ << 4) + h) * LL + l1) * HD + hd) = h2u(v1.x, v1.y);
            }
        }
    }
}

// ---------------- tensor-core flash attention (fp16 in/out, cp.async) --------
#define FS 72
#define KVB (64 * FS * 2)    // bytes per K (or V) buffer

__global__ __launch_bounds__(128)
void flash_mma(const __half* __restrict__ Q, const __half* __restrict__ Kg,
               const __half* __restrict__ Vg, __half* __restrict__ O)
{
    __shared__ __align__(16) uint16_t Qs[64][FS];
    __shared__ __align__(16) uint16_t Ks[2][64][FS];
    __shared__ __align__(16) uint16_t Vs[2][64][FS];

    const int tid  = threadIdx.x;
    const int wid  = tid >> 5;
    const int lane = tid & 31;
    const int grp  = lane >> 2;
    const int lg   = lane & 3;
    const int bh   = blockIdx.y;
    const int q0   = blockIdx.x * 64;

    const int lrow = tid >> 1, lcol = (tid & 1) * 32;   // 32 halves each

    const uint32_t Qb_s = (uint32_t)__cvta_generic_to_shared(&Qs[0][0]);
    const uint32_t Kb_s = (uint32_t)__cvta_generic_to_shared(&Ks[0][0][0]);
    const uint32_t Vb_s = (uint32_t)__cvta_generic_to_shared(&Vs[0][0][0]);

    const uint32_t q_dst = Qb_s + lrow * (FS * 2) + lcol * 2;
    const uint32_t k_dst = Kb_s + lrow * (FS * 2) + lcol * 2;
    const uint32_t v_dst = Vb_s + lrow * (FS * 2) + lcol * 2;
    const __half* Qp = Q + ((size_t)bh * LL + q0 + lrow) * HD + lcol;
    const __half* Kp = Kg + ((size_t)bh * LL + lrow) * HD + lcol;
    const __half* Vp = Vg + ((size_t)bh * LL + lrow) * HD + lcol;

    // stage Q (own group)
    #pragma unroll
    for (int i = 0; i < 4; i++) cp16(q_dst + i * 16, Qp + i * 8);
    CP_COMMIT();
    // prefetch KV tiles 0,1
    #pragma unroll
    for (int pt = 0; pt < 2; pt++) {
        #pragma unroll
        for (int i = 0; i < 4; i++) {
            cp16(k_dst + pt * KVB + i * 16, Kp + (size_t)pt * 64 * HD + i * 8);
            cp16(v_dst + pt * KVB + i * 16, Vp + (size_t)pt * 64 * HD + i * 8);
        }
        CP_COMMIT();
    }

    // Q a-fragments (resident)
    CP_WAIT(2);
    __syncthreads();
    uint32_t qa[4][4];
    {
        const uint32_t qaddr = Qb_s + ((wid * 16 + (lane & 15)) * FS + (lane >> 4) * 8) * 2;
        #pragma unroll
        for (int ks = 0; ks < 4; ks++)
            ldm_x4(qa[ks][0], qa[ks][1], qa[ks][2], qa[ks][3], qaddr + ks * 16 * 2);
    }

    const uint32_t kaddr = Kb_s +
        (((lane >> 4) * 8 + (lane & 7)) * FS + ((lane >> 3) & 1) * 8) * 2;
    const uint32_t vaddr = Vb_s + ((lane & 15) * FS) * 2;

    float m0 = -1e30f, m1 = -1e30f, l0 = 0.f, l1 = 0.f;
    float oacc[8][4];
    #pragma unroll
    for (int j = 0; j < 8; j++)
        #pragma unroll
        for (int q = 0; q < 4; q++) oacc[j][q] = 0.f;

    const int NT = LL / 64;
    for (int kt = 0; kt < NT; kt++) {
        const int buf = kt & 1;
        CP_WAIT(1);
        __syncthreads();

        // ---- S = Q @ K^T ----
        float sacc[8][4];
        #pragma unroll
        for (int na = 0; na < 8; na++)
            #pragma unroll
            for (int q = 0; q < 4; q++) sacc[na][q] = 0.f;

        #pragma unroll
        for (int ks = 0; ks < 4; ks++) {
            #pragma unroll
            for (int na2 = 0; na2 < 4; na2++) {
                uint32_t b0, b1, b2, b3;
                ldm_x4(b0, b1, b2, b3,
                       kaddr + buf * KVB + (na2 * 16 * FS + ks * 16) * 2);
                uint32_t bb0[2] = {b0, b1};
                uint32_t bb1[2] = {b2, b3};
                mma_f16(sacc[na2 * 2], qa[ks], bb0);
                mma_f16(sacc[na2 * 2 + 1], qa[ks], bb1);
            }
        }
        // apply 1/sqrt(HD)
        #pragma unroll
        for (int na = 0; na < 8; na++) {
            sacc[na][0] *= 0.125f; sacc[na][1] *= 0.125f;
            sacc[na][2] *= 0.125f; sacc[na][3] *= 0.125f;
        }

        // ---- online softmax ----
        float tm0 = -1e30f, tm1 = -1e30f;
        #pragma unroll
        for (int na = 0; na < 8; na++) {
            tm0 = fmaxf(tm0, fmaxf(sacc[na][0], sacc[na][1]));
            tm1 = fmaxf(tm1, fmaxf(sacc[na][2], sacc[na][3]));
        }
        tm0 = fmaxf(tm0, __shfl_xor_sync(0xffffffffu, tm0, 1));
        tm0 = fmaxf(tm0, __shfl_xor_sync(0xffffffffu, tm0, 2));
        tm1 = fmaxf(tm1, __shfl_xor_sync(0xffffffffu, tm1, 1));
        tm1 = fmaxf(tm1, __shfl_xor_sync(0xffffffffu, tm1, 2));
        const float nm0 = fmaxf(m0, tm0), nm1 = fmaxf(m1, tm1);
        const float f0 = __expf(m0 - nm0), f1 = __expf(m1 - nm1);
        m0 = nm0; m1 = nm1;

        float s0 = 0.f, s1 = 0.f;
        uint32_t pa[4][4];
        #pragma unroll
        for (int na = 0; na < 8; na++) {
            float p0 = __expf(sacc[na][0] - nm0);
            float p1 = __expf(sacc[na][1] - nm0);
            float p2 = __expf(sacc[na][2] - nm1);
            float p3 = __expf(sacc[na][3] - nm1);
            s0 += p0 + p1; s1 += p2 + p3;
            pa[na >> 1][(na & 1) * 2 + 0] = h2u(p0, p1);
            pa[na >> 1][(na & 1) * 2 + 1] = h2u(p2, p3);
        }
        s0 += __shfl_xor_sync(0xffffffffu, s0, 1);
        s0 += __shfl_xor_sync(0xffffffffu, s0, 2);
        s1 += __shfl_xor_sync(0xffffffffu, s1, 1);
        s1 += __shfl_xor_sync(0xffffffffu, s1, 2);
        l0 = l0 * f0 + s0;
        l1 = l1 * f1 + s1;
        #pragma unroll
        for (int j = 0; j < 8; j++) {
            oacc[j][0] *= f0; oacc[j][1] *= f0;
            oacc[j][2] *= f1; oacc[j][3] *= f1;
        }

        // ---- O += P @ V ----
        #pragma unroll
        for (int ks = 0; ks < 4; ks++) {
            #pragma unroll
            for (int j = 0; j < 8; j++) {
                uint32_t b0, b1;
                ldm_x2t(b0, b1, vaddr + buf * KVB + (ks * 16 * FS + j * 8) * 2);
                uint32_t bb[2] = {b0, b1};
                mma_f16(oacc[j], pa[ks], bb);
            }
        }
        __syncthreads();
        if (kt + 2 < NT) {
            #pragma unroll
            for (int i = 0; i < 4; i++) {
                cp16(k_dst + buf * KVB + i * 16, Kp + (size_t)(kt + 2) * 64 * HD + i * 8);
                cp16(v_dst + buf * KVB + i * 16, Vp + (size_t)(kt + 2) * 64 * HD + i * 8);
            }
        }
        CP_COMMIT();
    }

    // ---- write merged-head fp16 output ----
    const float inv0 = 1.f / l0, inv1 = 1.f / l1;
    const int b = bh >> 4, h = bh & 15;
    const int r0 = q0 + wid * 16 + grp;
    __half* O0 = O + ((size_t)(b * LL + r0)) * DM + h * HD;
    __half* O1 = O0 + (size_t)8 * DM;
    #pragma unroll
    for (int j = 0; j < 8; j++) {
        *(uint32_t*)(O0 + j * 8 + 2 * lg) = h2u(oacc[j][0] * inv0, oacc[j][1] * inv0);
        *(uint32_t*)(O1 + j * 8 + 2 * lg) = h2u(oacc[j][2] * inv1, oacc[j][3] * inv1);
    }
}

// ---------------- fused residual add + LayerNorm (optional fp16 copy) -------
template<bool WRITE_H>
__global__ __launch_bounds__(256)
void add_ln_k(const float* __restrict__ A, const float* __restrict__ B,
              const float* __restrict__ gamma, const float* __restrict__ beta,
              float* __restrict__ out, __half* __restrict__ outh)
{
    const int row = blockIdx.x, t = threadIdx.x;
    const float4* a = (const float4*)(A + (size_t)row * DM);
    const float4* b = (const float4*)(B + (size_t)row * DM);
    float4 v = a[t], w = b[t];
    v.x += w.x; v.y += w.y; v.z += w.z; v.w += w.w;

    float s = v.x + v.y + v.z + v.w;
    float q = v.x * v.x + v.y * v.y + v.z * v.z + v.w * v.w;
    #pragma unroll
    for (int o = 16; o > 0; o >>= 1) {
        s += __shfl_xor_sync(0xffffffffu, s, o);
        q += __shfl_xor_sync(0xffffffffu, q, o);
    }
    __shared__ float ss[8], sq[8];
    const int wid = t >> 5, lane = t & 31;
    if (lane == 0) { ss[wid] = s; sq[wid] = q; }
    __syncthreads();
    s = 0.f; q = 0.f;
    #pragma unroll
    for (int i = 0; i < 8; i++) { s += ss[i]; q += sq[i]; }

    const float mean = s * (1.f / DM);
    const float var  = q * (1.f / DM) - mean * mean;
    const float rstd = rsqrtf(var + 1e-5f);

    const int c = t * 4;
    float4 g  = *(const float4*)(gamma + c);
    float4 be = *(const float4*)(beta + c);
    float4 o;
    o.x = (v.x - mean) * rstd * g.x + be.x;
    o.y = (v.y - mean) * rstd * g.y + be.y;
    o.z = (v.z - mean) * rstd * g.z + be.z;
    o.w = (v.w - mean) * rstd * g.w + be.w;
    ((float4*)(out + (size_t)row * DM))[t] = o;
    if (WRITE_H) {
        uint2 hh = make_uint2(h2u(o.x, o.y), h2u(o.z, o.w));
        *(uint2*)(outh + (size_t)row * DM + c) = hh;
    }
}

// ---------------- launcher ---------------------------------------------------
extern "C" void kernel_launch(void* const* d_in, const int* in_sizes, int n_in,
                              void* d_out, int out_size)
{
    const float* src = (const float*)d_in[0];
    const float* Wq  = (const float*)d_in[1];  const float* bq = (const float*)d_in[2];
    const float* Wk  = (const float*)d_in[3];  const float* bk = (const float*)d_in[4];
    const float* Wv  = (const float*)d_in[5];  const float* bv = (const float*)d_in[6];
    const float* Wo  = (const float*)d_in[7];  const float* bo = (const float*)d_in[8];
    const float* W1  = (const float*)d_in[9];  const float* b1 = (const float*)d_in[10];
    const float* W2  = (const float*)d_in[11]; const float* b2 = (const float*)d_in[12];
    const float* gamma1 = (const float*)d_in[13]; const float* beta1 = (const float*)d_in[14];
    const float* gamma2 = (const float*)d_in[15]; const float* beta2 = (const float*)d_in[16];
    float* out = (float*)d_out;

    __half *srch, *Wqh, *Wkh, *Wvh, *Woh, *W1h, *W2h;
    __half *Qh, *Kh, *Vh, *attnh, *xh, *ff1h;
    float  *proj, *x, *ff2;
    cudaGetSymbolAddress((void**)&srch,  g_srch);
    cudaGetSymbolAddress((void**)&Wqh,   g_Wqh);
    cudaGetSymbolAddress((void**)&Wkh,   g_Wkh);
    cudaGetSymbolAddress((void**)&Wvh,   g_Wvh);
    cudaGetSymbolAddress((void**)&Woh,   g_Woh);
    cudaGetSymbolAddress((void**)&W1h,   g_W1h);
    cudaGetSymbolAddress((void**)&W2h,   g_W2h);
    cudaGetSymbolAddress((void**)&Qh,    g_Qh);
    cudaGetSymbolAddress((void**)&Kh,    g_Kh);
    cudaGetSymbolAddress((void**)&Vh,    g_Vh);
    cudaGetSymbolAddress((void**)&attnh, g_attnh);
    cudaGetSymbolAddress((void**)&xh,    g_xh);
    cudaGetSymbolAddress((void**)&ff1h,  g_ff1h);
    cudaGetSymbolAddress((void**)&proj,  g_proj);
    cudaGetSymbolAddress((void**)&x,     g_x);
    cudaGetSymbolAddress((void**)&ff2,   g_ff2);

    // one-shot fp16 conversions
    f2h_k<<<(MTOT * DM / 8 + 255) / 256, 256>>>(src, srch, MTOT * DM);
    f2h_k<<<(DM * DM / 8 + 255) / 256, 256>>>(Wq, Wqh, DM * DM);
    f2h_k<<<(DM * DM / 8 + 255) / 256, 256>>>(Wk, Wkh, DM * DM);
    f2h_k<<<(DM * DM / 8 + 255) / 256, 256>>>(Wv, Wvh, DM * DM);
    f2h_k<<<(DM * DM / 8 + 255) / 256, 256>>>(Wo, Woh, DM * DM);
    f2h_k<<<(DM * DFF / 8 + 255) / 256, 256>>>(W1, W1h, DM * DFF);
    f2h_k<<<(DFF * DM / 8 + 255) / 256, 256>>>(W2, W2h, DFF * DM);

    // QKV projections (split-heads fp16)
    wm_gemm<2><<<dim3(DM / 128, MTOT / 128), 256>>>(srch, Wqh, bq, Qh, MTOT, DM, DM);
    wm_gemm<2><<<dim3(DM / 128, MTOT / 128), 256>>>(srch, Wkh, bk, Kh, MTOT, DM, DM);
    wm_gemm<2><<<dim3(DM / 128, MTOT / 128), 256>>>(srch, Wvh, bv, Vh, MTOT, DM, DM);

    // flash attention (fp16 -> fp16 merged-head)
    flash_mma<<<dim3(LL / 64, BB * NH), 128>>>(Qh, Kh, Vh, attnh);

    // output projection (fp32 out)
    wm_gemm<0><<<dim3(DM / 128, MTOT / 128), 256>>>(attnh, Woh, bo, proj, MTOT, DM, DM);

    // x = LN(src + proj), dual fp32/fp16
    add_ln_k<true><<<MTOT, 256>>>(src, proj, gamma1, beta1, x, xh);

    // FF
    wm_gemm<1><<<dim3(DFF / 128, MTOT / 128), 256>>>(xh, W1h, b1, ff1h, MTOT, DFF, DM);
    wm_gemm<0><<<dim3(DM / 128, MTOT / 128), 256>>>(ff1h, W2h, b2, ff2, MTOT, DM, DFF);

    // out = LN(x + ff)
    add_ln_k<false><<<MTOT, 256>>>(x, ff2, gamma2, beta2, out, nullptr);
}

// round 7
// speedup vs baseline: 6.6559x; 1.0028x over previous
#include <cuda_runtime.h>
#include <cuda_fp16.h>
#include <math.h>
#include <cstdint>

#define DM   1024
#define NH   16
#define HD   64
#define DFF  4096
#define BB   2
#define LL   2048
#define MTOT (BB*LL)
#define HSZ  ((size_t)NH*BB*LL*HD)      // per-tensor Q/K/V size

// ---------------- scratch (static device globals; allocation-free) ----------
__device__ __half g_srch[(size_t)MTOT*DM];
__device__ __half g_Wqkvh[(size_t)DM*3*DM];   // [k][3072] concat q|k|v
__device__ float  g_bqkv[3*DM];
__device__ __half g_Woh[(size_t)DM*DM];
__device__ __half g_W1h[(size_t)DM*DFF];
__device__ __half g_W2h[(size_t)DFF*DM];
__device__ __half g_QKVh[3*HSZ];              // split-head Q|K|V
__device__ __half g_attnh[(size_t)MTOT*DM];
__device__ float  g_proj[(size_t)MTOT*DM];
__device__ float  g_x[(size_t)MTOT*DM];
__device__ __half g_xh[(size_t)MTOT*DM];
__device__ __half g_ff1h[(size_t)MTOT*DFF];
__device__ float  g_ff2[(size_t)MTOT*DM];

// ---------------- helpers ------------------------------------------------------
__device__ __forceinline__ void mma_f16(float* d, const uint32_t* a, const uint32_t* b) {
    asm volatile(
        "mma.sync.aligned.m16n8k16.row.col.f32.f16.f16.f32 "
        "{%0,%1,%2,%3}, {%4,%5,%6,%7}, {%8,%9}, {%0,%1,%2,%3};"
        : "+f"(d[0]), "+f"(d[1]), "+f"(d[2]), "+f"(d[3])
        : "r"(a[0]), "r"(a[1]), "r"(a[2]), "r"(a[3]), "r"(b[0]), "r"(b[1]));
}
__device__ __forceinline__ void ldm_x4(uint32_t& r0, uint32_t& r1, uint32_t& r2, uint32_t& r3,
                                       uint32_t addr) {
    asm volatile("ldmatrix.sync.aligned.m8n8.x4.shared.b16 {%0,%1,%2,%3}, [%4];"
                 : "=r"(r0), "=r"(r1), "=r"(r2), "=r"(r3) : "r"(addr));
}
__device__ __forceinline__ void ldm_x4t(uint32_t& r0, uint32_t& r1, uint32_t& r2, uint32_t& r3,
                                        uint32_t addr) {
    asm volatile("ldmatrix.sync.aligned.m8n8.x4.trans.shared.b16 {%0,%1,%2,%3}, [%4];"
                 : "=r"(r0), "=r"(r1), "=r"(r2), "=r"(r3) : "r"(addr));
}
__device__ __forceinline__ uint32_t h2u(float x, float y) {
    __half2 h = __float22half2_rn(make_float2(x, y));
    return *(uint32_t*)&h;
}
__device__ __forceinline__ void cp16(uint32_t dst, const void* src) {
    asm volatile("cp.async.cg.shared.global [%0], [%1], 16;" :: "r"(dst), "l"(src));
}
#define CP_COMMIT() asm volatile("cp.async.commit_group;" ::: "memory")
#define CP_WAIT(N)  asm volatile("cp.async.wait_group %0;" :: "n"(N) : "memory")

// ---------------- one-shot conversion / concat kernel -------------------------
#define SRC_E (4194304u)
#define WE    (1048576u)

__device__ __forceinline__ void cvt8(const float* in, __half* out) {
    float4 a = *(const float4*)in;
    float4 b = *(const float4*)(in + 4);
    uint4 o;
    o.x = h2u(a.x, a.y); o.y = h2u(a.z, a.w);
    o.z = h2u(b.x, b.y); o.w = h2u(b.z, b.w);
    *(uint4*)out = o;
}

__global__ __launch_bounds__(256)
void conv_all(const float* __restrict__ src,
              const float* __restrict__ Wq, const float* __restrict__ Wk,
              const float* __restrict__ Wv, const float* __restrict__ Wo,
              const float* __restrict__ W1, const float* __restrict__ W2,
              const float* __restrict__ bq, const float* __restrict__ bk,
              const float* __restrict__ bv,
              __half* __restrict__ srch, __half* __restrict__ Wqkv,
              __half* __restrict__ Woh, __half* __restrict__ W1h,
              __half* __restrict__ W2h, float* __restrict__ bqkv)
{
    const unsigned g = blockIdx.x * 256 + threadIdx.x;
    if (g < 384) {                    // concat biases: 3 x 1024 floats
        int t = g >> 7;
        int i = (g & 127) * 8;
        const float* bp = (t == 0) ? bq : (t == 1) ? bk : bv;
        float4 a = *(const float4*)(bp + i);
        float4 b = *(const float4*)(bp + i + 4);
        *(float4*)(bqkv + t * 1024 + i)     = a;
        *(float4*)(bqkv + t * 1024 + i + 4) = b;
    }
    size_t i = (size_t)g * 8;
    if (i < SRC_E) {
        cvt8(src + i, srch + i);
    } else if (i < SRC_E + 3 * (size_t)WE) {          // Wq|Wk|Wv -> [k][3072]
        size_t j = i - SRC_E;
        int t = (int)(j >> 20);
        size_t jj = j & (WE - 1);
        const float* W = (t == 0) ? Wq : (t == 1) ? Wk : Wv;
        size_t k = jj >> 10, n = jj & 1023;
        cvt8(W + jj, Wqkv + k * 3072 + t * 1024 + n);
    } else if (i < SRC_E + 4 * (size_t)WE) {
        size_t j = i - (SRC_E + 3 * (size_t)WE);
        cvt8(Wo + j, Woh + j);
    } else if (i < SRC_E + 4 * (size_t)WE + SRC_E) {
        size_t j = i - (SRC_E + 4 * (size_t)WE);
        cvt8(W1 + j, W1h + j);
    } else {
        size_t j = i - (SRC_E + 4 * (size_t)WE + SRC_E);
        cvt8(W2 + j, W2h + j);
    }
}

// ---------------- warp-mma FP16 GEMM, 3-stage cp.async, single-sync ----------
// EPI 0: fp32 plain  1: gelu fp16  2: split-head qkv-concat fp16 (N=3072)
#define KC 32
#define AS_STRIDE 40
#define BS_STRIDE 136
#define ASB (128 * AS_STRIDE * 2)     // 10240 B / buffer
#define BSB (KC * BS_STRIDE * 2)      // 8704 B / buffer
#define GEMM_SMEM (3 * (ASB + BSB))   // 56832 B

template<int EPI>
__global__ __launch_bounds__(256)
void wm_gemm(const __half* __restrict__ A, const __half* __restrict__ B,
             const float* __restrict__ bias, void* __restrict__ Cv,
             int M, int N, int K)
{
    extern __shared__ __align__(16) char smem[];
    const uint32_t As_base = (uint32_t)__cvta_generic_to_shared(smem);
    const uint32_t Bs_base = As_base + 3 * ASB;

    const int tid  = threadIdx.x;
    const int wid  = tid >> 5;
    const int lane = tid & 31;
    const int lg   = lane & 3;
    const int grp  = lane >> 2;
    const int n0 = blockIdx.x * 128;
    const int m0 = blockIdx.y * 128;
    const int wm = (wid & 3) * 32;
    const int wn = (wid >> 2) * 64;

    // staging
    const int arow = tid >> 1, acol = (tid & 1) * 16;
    const int brow = tid >> 3, bcol = (tid & 7) * 16;
    const __half* Ap = A + (size_t)(m0 + arow) * K + acol;
    const __half* Bp = B + (size_t)brow * N + n0 + bcol;
    const uint32_t a_dst = As_base + arow * (AS_STRIDE * 2) + acol * 2;
    const uint32_t b_dst = Bs_base + brow * (BS_STRIDE * 2) + bcol * 2;

    // ldmatrix addresses
    const uint32_t a_addr0 = As_base +
        ((wm + (lane & 15)) * AS_STRIDE + (lane >> 4) * 8) * 2;
    const uint32_t b_addr0 = Bs_base +
        ((lane & 15) * BS_STRIDE + wn + (lane >> 4) * 8) * 2;

    float d[2][8][4];
    #pragma unroll
    for (int i = 0; i < 2; i++)
        #pragma unroll
        for (int j = 0; j < 8; j++)
            #pragma unroll
            for (int q = 0; q < 4; q++) d[i][j][q] = 0.f;

    const int C_CHUNKS = K >> 5;

    #pragma unroll
    for (int pc = 0; pc < 2; pc++) {
        cp16(a_dst + pc * ASB,      Ap + pc * KC);
        cp16(a_dst + pc * ASB + 16, Ap + pc * KC + 8);
        cp16(b_dst + pc * BSB,      Bp + (size_t)pc * KC * N);
        cp16(b_dst + pc * BSB + 16, Bp + (size_t)pc * KC * N + 8);
        CP_COMMIT();
    }

    for (int c = 0; c < C_CHUNKS; c++) {
        const int rb = c % 3;
        CP_WAIT(1);
        __syncthreads();
        if (c + 2 < C_CHUNKS) {
            const int wb = (c + 2) % 3;
            cp16(a_dst + wb * ASB,      Ap + (c + 2) * KC);
            cp16(a_dst + wb * ASB + 16, Ap + (c + 2) * KC + 8);
            cp16(b_dst + wb * BSB,      Bp + (size_t)(c + 2) * KC * N);
            cp16(b_dst + wb * BSB + 16, Bp + (size_t)(c + 2) * KC * N + 8);
        }
        CP_COMMIT();

        #pragma unroll
        for (int ks = 0; ks < 2; ks++) {
            uint32_t a[2][4], b[8][2];
            #pragma unroll
            for (int i = 0; i < 2; i++)
                ldm_x4(a[i][0], a[i][1], a[i][2], a[i][3],
                       a_addr0 + rb * ASB + (i * 16 * AS_STRIDE + ks * 16) * 2);
            #pragma unroll
            for (int j2 = 0; j2 < 4; j2++) {
                uint32_t r0, r1, r2, r3;
                ldm_x4t(r0, r1, r2, r3,
                        b_addr0 + rb * BSB + (ks * 16 * BS_STRIDE + j2 * 16) * 2);
                b[j2 * 2][0] = r0; b[j2 * 2][1] = r1;
                b[j2 * 2 + 1][0] = r2; b[j2 * 2 + 1][1] = r3;
            }
            #pragma unroll
            for (int i = 0; i < 2; i++)
                #pragma unroll
                for (int j = 0; j < 8; j++)
                    mma_f16(d[i][j], a[i], b[j]);
        }
    }

    // ---- epilogue ----
    #pragma unroll
    for (int i = 0; i < 2; i++) {
        const int r0 = m0 + wm + i * 16 + grp;
        #pragma unroll
        for (int j = 0; j < 8; j++) {
            const int c = n0 + wn + j * 8 + lg * 2;
            float2 v0, v1;
            v0.x = d[i][j][0] + bias[c];
            v0.y = d[i][j][1] + bias[c + 1];
            v1.x = d[i][j][2] + bias[c];
            v1.y = d[i][j][3] + bias[c + 1];
            if (EPI == 0) {
                float* C = (float*)Cv;
                *(float2*)(C + (size_t)r0 * N + c) = v0;
                *(float2*)(C + (size_t)(r0 + 8) * N + c) = v1;
            } else if (EPI == 1) {
                v0.x *= normcdff(v0.x); v0.y *= normcdff(v0.y);
                v1.x *= normcdff(v1.x); v1.y *= normcdff(v1.y);
                __half* C = (__half*)Cv;
                *(uint32_t*)(C + (size_t)r0 * N + c) = h2u(v0.x, v0.y);
                *(uint32_t*)(C + (size_t)(r0 + 8) * N + c) = h2u(v1.x, v1.y);
            } else {
                const int t_ = c >> 10, n = c & 1023;
                const int h = n >> 6, hd = n & 63;
                const int b0_ = r0 >> 11, l0 = r0 & 2047;
                const int r1 = r0 + 8;
                const int b1_ = r1 >> 11, l1 = r1 & 2047;
                __half* C = (__half*)Cv + (size_t)t_ * HSZ;
                *(uint32_t*)(C + ((size_t)((b0_ << 4) + h) * LL + l0) * HD + hd) = h2u(v0.x, v0.y);
                *(uint32_t*)(C + ((size_t)((b1_ << 4) + h) * LL + l1) * HD + hd) = h2u(v1.x, v1.y);
            }
        }
    }
}

// ---------------- tensor-core flash attention (fp16, cp.async, x4t V) --------
#define FS 72
#define KVB (64 * FS * 2)

__global__ __launch_bounds__(128)
void flash_mma(const __half* __restrict__ Q, const __half* __restrict__ Kg,
               const __half* __restrict__ Vg, __half* __restrict__ O)
{
    __shared__ __align__(16) uint16_t Qs[64][FS];
    __shared__ __align__(16) uint16_t Ks[2][64][FS];
    __shared__ __align__(16) uint16_t Vs[2][64][FS];

    const int tid  = threadIdx.x;
    const int wid  = tid >> 5;
    const int lane = tid & 31;
    const int grp  = lane >> 2;
    const int lg   = lane & 3;
    const int bh   = blockIdx.y;
    const int q0   = blockIdx.x * 64;

    const int lrow = tid >> 1, lcol = (tid & 1) * 32;

    const uint32_t Qb_s = (uint32_t)__cvta_generic_to_shared(&Qs[0][0]);
    const uint32_t Kb_s = (uint32_t)__cvta_generic_to_shared(&Ks[0][0][0]);
    const uint32_t Vb_s = (uint32_t)__cvta_generic_to_shared(&Vs[0][0][0]);

    const uint32_t q_dst = Qb_s + lrow * (FS * 2) + lcol * 2;
    const uint32_t k_dst = Kb_s + lrow * (FS * 2) + lcol * 2;
    const uint32_t v_dst = Vb_s + lrow * (FS * 2) + lcol * 2;
    const __half* Qp = Q + ((size_t)bh * LL + q0 + lrow) * HD + lcol;
    const __half* Kp = Kg + ((size_t)bh * LL + lrow) * HD + lcol;
    const __half* Vp = Vg + ((size_t)bh * LL + lrow) * HD + lcol;

    #pragma unroll
    for (int i = 0; i < 4; i++) cp16(q_dst + i * 16, Qp + i * 8);
    CP_COMMIT();
    #pragma unroll
    for (int pt = 0; pt < 2; pt++) {
        #pragma unroll
        for (int i = 0; i < 4; i++) {
            cp16(k_dst + pt * KVB + i * 16, Kp + (size_t)pt * 64 * HD + i * 8);
            cp16(v_dst + pt * KVB + i * 16, Vp + (size_t)pt * 64 * HD + i * 8);
        }
        CP_COMMIT();
    }

    CP_WAIT(2);
    __syncthreads();
    uint32_t qa[4][4];
    {
        const uint32_t qaddr = Qb_s + ((wid * 16 + (lane & 15)) * FS + (lane >> 4) * 8) * 2;
        #pragma unroll
        for (int ks = 0; ks < 4; ks++)
            ldm_x4(qa[ks][0], qa[ks][1], qa[ks][2], qa[ks][3], qaddr + ks * 16 * 2);
    }

    const uint32_t kaddr = Kb_s +
        (((lane >> 4) * 8 + (lane & 7)) * FS + ((lane >> 3) & 1) * 8) * 2;
    const uint32_t vaddr = Vb_s + ((lane & 15) * FS + (lane >> 4) * 8) * 2;

    float m0 = -1e30f, m1 = -1e30f, l0 = 0.f, l1 = 0.f;
    float oacc[8][4];
    #pragma unroll
    for (int j = 0; j < 8; j++)
        #pragma unroll
        for (int q = 0; q < 4; q++) oacc[j][q] = 0.f;

    const int NT = LL / 64;
    for (int kt = 0; kt < NT; kt++) {
        const int buf = kt & 1;
        CP_WAIT(1);
        __syncthreads();

        float sacc[8][4];
        #pragma unroll
        for (int na = 0; na < 8; na++)
            #pragma unroll
            for (int q = 0; q < 4; q++) sacc[na][q] = 0.f;

        #pragma unroll
        for (int ks = 0; ks < 4; ks++) {
            #pragma unroll
            for (int na2 = 0; na2 < 4; na2++) {
                uint32_t b0, b1, b2, b3;
                ldm_x4(b0, b1, b2, b3,
                       kaddr + buf * KVB + (na2 * 16 * FS + ks * 16) * 2);
                uint32_t bb0[2] = {b0, b1};
                uint32_t bb1[2] = {b2, b3};
                mma_f16(sacc[na2 * 2], qa[ks], bb0);
                mma_f16(sacc[na2 * 2 + 1], qa[ks], bb1);
            }
        }
        #pragma unroll
        for (int na = 0; na < 8; na++) {
            sacc[na][0] *= 0.125f; sacc[na][1] *= 0.125f;
            sacc[na][2] *= 0.125f; sacc[na][3] *= 0.125f;
        }

        float tm0 = -1e30f, tm1 = -1e30f;
        #pragma unroll
        for (int na = 0; na < 8; na++) {
            tm0 = fmaxf(tm0, fmaxf(sacc[na][0], sacc[na][1]));
            tm1 = fmaxf(tm1, fmaxf(sacc[na][2], sacc[na][3]));
        }
        tm0 = fmaxf(tm0, __shfl_xor_sync(0xffffffffu, tm0, 1));
        tm0 = fmaxf(tm0, __shfl_xor_sync(0xffffffffu, tm0, 2));
        tm1 = fmaxf(tm1, __shfl_xor_sync(0xffffffffu, tm1, 1));
        tm1 = fmaxf(tm1, __shfl_xor_sync(0xffffffffu, tm1, 2));
        const float nm0 = fmaxf(m0, tm0), nm1 = fmaxf(m1, tm1);
        const float f0 = __expf(m0 - nm0), f1 = __expf(m1 - nm1);
        m0 = nm0; m1 = nm1;

        float s0 = 0.f, s1 = 0.f;
        uint32_t pa[4][4];
        #pragma unroll
        for (int na = 0; na < 8; na++) {
            float p0 = __expf(sacc[na][0] - nm0);
            float p1 = __expf(sacc[na][1] - nm0);
            float p2 = __expf(sacc[na][2] - nm1);
            float p3 = __expf(sacc[na][3] - nm1);
            s0 += p0 + p1; s1 += p2 + p3;
            pa[na >> 1][(na & 1) * 2 + 0] = h2u(p0, p1);
            pa[na >> 1][(na & 1) * 2 + 1] = h2u(p2, p3);
        }
        s0 += __shfl_xor_sync(0xffffffffu, s0, 1);
        s0 += __shfl_xor_sync(0xffffffffu, s0, 2);
        s1 += __shfl_xor_sync(0xffffffffu, s1, 1);
        s1 += __shfl_xor_sync(0xffffffffu, s1, 2);
        l0 = l0 * f0 + s0;
        l1 = l1 * f1 + s1;
        #pragma unroll
        for (int j = 0; j < 8; j++) {
            oacc[j][0] *= f0; oacc[j][1] *= f0;
            oacc[j][2] *= f1; oacc[j][3] *= f1;
        }

        #pragma unroll
        for (int ks = 0; ks < 4; ks++) {
            #pragma unroll
            for (int j2 = 0; j2 < 4; j2++) {
                uint32_t r0, r1, r2, r3;
                ldm_x4t(r0, r1, r2, r3,
                        vaddr + buf * KVB + (ks * 16 * FS + j2 * 16) * 2);
                uint32_t bb0[2] = {r0, r1};
                uint32_t bb1[2] = {r2, r3};
                mma_f16(oacc[j2 * 2], pa[ks], bb0);
                mma_f16(oacc[j2 * 2 + 1], pa[ks], bb1);
            }
        }
        __syncthreads();
        if (kt + 2 < NT) {
            #pragma unroll
            for (int i = 0; i < 4; i++) {
                cp16(k_dst + buf * KVB + i * 16, Kp + (size_t)(kt + 2) * 64 * HD + i * 8);
                cp16(v_dst + buf * KVB + i * 16, Vp + (size_t)(kt + 2) * 64 * HD + i * 8);
            }
        }
        CP_COMMIT();
    }

    const float inv0 = 1.f / l0, inv1 = 1.f / l1;
    const int b = bh >> 4, h = bh & 15;
    const int r0 = q0 + wid * 16 + grp;
    __half* O0 = O + ((size_t)(b * LL + r0)) * DM + h * HD;
    __half* O1 = O0 + (size_t)8 * DM;
    #pragma unroll
    for (int j = 0; j < 8; j++) {
        *(uint32_t*)(O0 + j * 8 + 2 * lg) = h2u(oacc[j][0] * inv0, oacc[j][1] * inv0);
        *(uint32_t*)(O1 + j * 8 + 2 * lg) = h2u(oacc[j][2] * inv1, oacc[j][3] * inv1);
    }
}

// ---------------- fused residual add + LayerNorm (optional fp16 copy) -------
template<bool WRITE_H>
__global__ __launch_bounds__(256)
void add_ln_k(const float* __restrict__ A, const float* __restrict__ B,
              const float* __restrict__ gamma, const float* __restrict__ beta,
              float* __restrict__ out, __half* __restrict__ outh)
{
    const int row = blockIdx.x, t = threadIdx.x;
    const float4* a = (const float4*)(A + (size_t)row * DM);
    const float4* b = (const float4*)(B + (size_t)row * DM);
    float4 v = a[t], w = b[t];
    v.x += w.x; v.y += w.y; v.z += w.z; v.w += w.w;

    float s = v.x + v.y + v.z + v.w;
    float q = v.x * v.x + v.y * v.y + v.z * v.z + v.w * v.w;
    #pragma unroll
    for (int o = 16; o > 0; o >>= 1) {
        s += __shfl_xor_sync(0xffffffffu, s, o);
        q += __shfl_xor_sync(0xffffffffu, q, o);
    }
    __shared__ float ss[8], sq[8];
    const int wid = t >> 5, lane = t & 31;
    if (lane == 0) { ss[wid] = s; sq[wid] = q; }
    __syncthreads();
    s = 0.f; q = 0.f;
    #pragma unroll
    for (int i = 0; i < 8; i++) { s += ss[i]; q += sq[i]; }

    const float mean = s * (1.f / DM);
    const float var  = q * (1.f / DM) - mean * mean;
    const float rstd = rsqrtf(var + 1e-5f);

    const int c = t * 4;
    float4 g  = *(const float4*)(gamma + c);
    float4 be = *(const float4*)(beta + c);
    float4 o;
    o.x = (v.x - mean) * rstd * g.x + be.x;
    o.y = (v.y - mean) * rstd * g.y + be.y;
    o.z = (v.z - mean) * rstd * g.z + be.z;
    o.w = (v.w - mean) * rstd * g.w + be.w;
    ((float4*)(out + (size_t)row * DM))[t] = o;
    if (WRITE_H) {
        uint2 hh = make_uint2(h2u(o.x, o.y), h2u(o.z, o.w));
        *(uint2*)(outh + (size_t)row * DM + c) = hh;
    }
}

// ---------------- launcher ---------------------------------------------------
extern "C" void kernel_launch(void* const* d_in, const int* in_sizes, int n_in,
                              void* d_out, int out_size)
{
    const float* src = (const float*)d_in[0];
    const float* Wq  = (const float*)d_in[1];  const float* bq = (const float*)d_in[2];
    const float* Wk  = (const float*)d_in[3];  const float* bk = (const float*)d_in[4];
    const float* Wv  = (const float*)d_in[5];  const float* bv = (const float*)d_in[6];
    const float* Wo  = (const float*)d_in[7];  const float* bo = (const float*)d_in[8];
    const float* W1  = (const float*)d_in[9];  const float* b1 = (const float*)d_in[10];
    const float* W2  = (const float*)d_in[11]; const float* b2 = (const float*)d_in[12];
    const float* gamma1 = (const float*)d_in[13]; const float* beta1 = (const float*)d_in[14];
    const float* gamma2 = (const float*)d_in[15]; const float* beta2 = (const float*)d_in[16];
    float* out = (float*)d_out;

    __half *srch, *Wqkvh, *Woh, *W1h, *W2h, *QKVh, *attnh, *xh, *ff1h;
    float  *bqkv, *proj, *x, *ff2;
    cudaGetSymbolAddress((void**)&srch,  g_srch);
    cudaGetSymbolAddress((void**)&Wqkvh, g_Wqkvh);
    cudaGetSymbolAddress((void**)&bqkv,  g_bqkv);
    cudaGetSymbolAddress((void**)&Woh,   g_Woh);
    cudaGetSymbolAddress((void**)&W1h,   g_W1h);
    cudaGetSymbolAddress((void**)&W2h,   g_W2h);
    cudaGetSymbolAddress((void**)&QKVh,  g_QKVh);
    cudaGetSymbolAddress((void**)&attnh, g_attnh);
    cudaGetSymbolAddress((void**)&xh,    g_xh);
    cudaGetSymbolAddress((void**)&ff1h,  g_ff1h);
    cudaGetSymbolAddress((void**)&proj,  g_proj);
    cudaGetSymbolAddress((void**)&x,     g_x);
    cudaGetSymbolAddress((void**)&ff2,   g_ff2);

    cudaFuncSetAttribute(wm_gemm<0>, cudaFuncAttributeMaxDynamicSharedMemorySize, GEMM_SMEM);
    cudaFuncSetAttribute(wm_gemm<1>, cudaFuncAttributeMaxDynamicSharedMemorySize, GEMM_SMEM);
    cudaFuncSetAttribute(wm_gemm<2>, cudaFuncAttributeMaxDynamicSharedMemorySize, GEMM_SMEM);

    // 1. convert + concat (16M elements / 8 per thread)
    conv_all<<<8192, 256>>>(src, Wq, Wk, Wv, Wo, W1, W2, bq, bk, bv,
                            srch, Wqkvh, Woh, W1h, W2h, bqkv);

    // 2. fused QKV projection (N=3072, split-head epilogue)
    wm_gemm<2><<<dim3(3 * DM / 128, MTOT / 128), 256, GEMM_SMEM>>>(
        srch, Wqkvh, bqkv, QKVh, MTOT, 3 * DM, DM);

    // 3. flash attention
    flash_mma<<<dim3(LL / 64, BB * NH), 128>>>(QKVh, QKVh + HSZ, QKVh + 2 * HSZ, attnh);

    // 4. output projection
    wm_gemm<0><<<dim3(DM / 128, MTOT / 128), 256, GEMM_SMEM>>>(attnh, Woh, bo, proj, MTOT, DM, DM);

    // 5. x = LN(src + proj)
    add_ln_k<true><<<MTOT, 256>>>(src, proj, gamma1, beta1, x, xh);

    // 6-7. FF
    wm_gemm<1><<<dim3(DFF / 128, MTOT / 128), 256, GEMM_SMEM>>>(xh, W1h, b1, ff1h, MTOT, DFF, DM);
    wm_gemm<0><<<dim3(DM / 128, MTOT / 128), 256, GEMM_SMEM>>>(ff1h, W2h, b2, ff2, MTOT, DM, DFF);

    // 8. out = LN(x + ff)
    add_ln_k<false><<<MTOT, 256>>>(x, ff2, gamma2, beta2, out, nullptr);
}